// round 12
// baseline (speedup 1.0000x reference)
#include <cuda_runtime.h>
#include <cuda_bf16.h>
#include <math.h>

// ---------------- problem constants ----------------
#define BATCH   8
#define SEQ     2048
#define TOK     (BATCH*SEQ)      // 16384
#define DMODEL  128
#define EMB     256
#define NLAYERS 3
#define NHEADS  8
#define HEADDIM 64
#define DSTATE  64
#define DCONV   4
#define DINNER  (NHEADS*HEADDIM)             // 512
#define DIP     (2*DINNER + 2*DSTATE + NHEADS) // 1160
#define CDIM    (DINNER + 2*DSTATE)          // 640
#define NFEAT   15

// ---------------- device scratch ----------------
__device__ float g_w[16];
__device__ float g_xn[TOK*EMB];
__device__ float g_x [TOK*EMB];
__device__ float g_z [TOK*DIP];
__device__ float g_xbc[TOK*CDIM];
__device__ float2 g_dtA[TOK*NHEADS];   // (.x = dt, .y = dA)
__device__ float g_y [TOK*DINNER];
__device__ float g_h1[TOK*EMB];

// ---------------- helpers ----------------
__device__ __forceinline__ float blockReduceSum(float v) {
    __shared__ float red[32];
    int lane = threadIdx.x & 31;
    int wid  = threadIdx.x >> 5;
    int nw   = (blockDim.x + 31) >> 5;
    #pragma unroll
    for (int o = 16; o; o >>= 1) v += __shfl_xor_sync(0xffffffffu, v, o);
    __syncthreads();
    if (lane == 0) red[wid] = v;
    __syncthreads();
    float tot = 0.f;
    for (int i = 0; i < nw; ++i) tot += red[i];
    return tot;
}

__device__ __forceinline__ float siluf(float x) { return x / (1.f + expf(-x)); }

__device__ __forceinline__ void mma_tf32(float* d, const unsigned* a, unsigned b0, unsigned b1) {
    asm volatile(
        "mma.sync.aligned.m16n8k8.row.col.f32.tf32.tf32.f32 "
        "{%0,%1,%2,%3},{%4,%5,%6,%7},{%8,%9},{%0,%1,%2,%3};\n"
        : "+f"(d[0]), "+f"(d[1]), "+f"(d[2]), "+f"(d[3])
        : "r"(a[0]), "r"(a[1]), "r"(a[2]), "r"(a[3]), "r"(b0), "r"(b1));
}

__device__ __forceinline__ void tf32_split(float x, unsigned& hi, unsigned& lo) {
    unsigned h;
    asm("cvt.rna.tf32.f32 %0, %1;\n" : "=r"(h) : "f"(x));
    float r = x - __uint_as_float(h);
    unsigned l;
    asm("cvt.rna.tf32.f32 %0, %1;\n" : "=r"(l) : "f"(r));
    hi = h; lo = l;
}

// ---------------- K0: softmax of w_avg ----------------
__global__ void softmax_kernel(const float* __restrict__ wa, int n) {
    if (threadIdx.x == 0) {
        float mx = -1e30f;
        for (int i = 0; i < n; ++i) mx = fmaxf(mx, wa[i]);
        float s = 0.f;
        for (int i = 0; i < n; ++i) { float e = expf(wa[i] - mx); g_w[i] = e; s += e; }
        float inv = 1.f / s;
        for (int i = 0; i < n; ++i) g_w[i] *= inv;
    }
}

// ---------------- K1: weighted feature average + layernorm(128) ----------------
__global__ void __launch_bounds__(128) avg_ln_kernel(
    const float* __restrict__ feat, const float* __restrict__ lg,
    const float* __restrict__ lb) {
    int r = blockIdx.x;
    int d = threadIdx.x;
    float acc = 0.f;
    #pragma unroll
    for (int f = 0; f < NFEAT; ++f)
        acc = fmaf(g_w[f], feat[((size_t)f * TOK + r) * DMODEL + d], acc);
    float m = blockReduceSum(acc) * (1.f / DMODEL);
    float dv = acc - m;
    float var = blockReduceSum(dv * dv) * (1.f / DMODEL);
    g_xn[(size_t)r * DMODEL + d] = dv * rsqrtf(var + 1e-5f) * lg[d] + lb[d];
}

// ---------------- 3xTF32 GEMM v2: split-at-STS, fused row-norm pre-ops ----------------
// C = epi( sc_row * (pre(A)(MxK) @ W(KxN)) )
// PRE: 0 = plain A
//      1 = rmsnorm fusion: store x*prew[k], sc_row = rsqrt(mean x^2 + eps)
//      2 = gate fusion:    g = y*silu(z); store g*prew[k], sc_row = rsqrt(mean g^2 + eps)
// EPI: 0=none 1=+bias 2=gelu(x+bias) 3=+residual
// Tiles BM=128 BN=128 BK=32; 8 warps (4m x 2n); warp tile 32x64.
// Smem planes hold (hi,lo) tf32 pairs as float2; LDS.64 fetches both terms at once.
#define ASF2 36
#define BSF2 132
#define ASF2_ELEMS (128*ASF2)
#define BSF2_ELEMS (32*BSF2)
#define TG2_SMEM ((2*ASF2_ELEMS + 2*BSF2_ELEMS)*8)

template<int PRE, int EPI>
__global__ void __launch_bounds__(256, 1) tgemm2_kernel(
    const float* __restrict__ A, const float* __restrict__ Az,
    const float* __restrict__ W, const float* __restrict__ prew,
    const float* __restrict__ bias, const float* __restrict__ res,
    float* __restrict__ C, int M, int N, int K)
{
    extern __shared__ float2 sm2[];
    float2* As[2] = { sm2, sm2 + ASF2_ELEMS };
    float2* Bs[2] = { sm2 + 2*ASF2_ELEMS, sm2 + 2*ASF2_ELEMS + BSF2_ELEMS };
    __shared__ float s_sc[128];

    int tid = threadIdx.x;
    int n0 = blockIdx.x * 128;
    int m0 = blockIdx.y * 128;
    int wid = tid >> 5, lane = tid & 31;
    int wm = wid >> 1, wn = wid & 1;
    int m0w = wm * 32, n0w = wn * 64;
    int g = lane >> 2, q = lane & 3;

    float acc[2][8][4];
    #pragma unroll
    for (int mi = 0; mi < 2; ++mi)
        #pragma unroll
        for (int ni = 0; ni < 8; ++ni)
            #pragma unroll
            for (int c = 0; c < 4; ++c) acc[mi][ni][c] = 0.f;

    int ar = tid >> 1, ak = (tid & 1) * 16;    // A: 2 threads per row, 16 k each
    int bk = tid & 31, bn = (tid >> 5) * 16;   // B: 1 k-row per lane-id, 16 n per warp

    float row_ss = 0.f;
    float4 rA[4], rZ[4], rB[4];

    auto loadG = [&](int k0) {
        const float* ag = A + (size_t)(m0 + ar) * K + k0 + ak;
        #pragma unroll
        for (int j = 0; j < 4; ++j) rA[j] = *(const float4*)(ag + j * 4);
        if (PRE == 2) {
            const float* zg = Az + (size_t)(m0 + ar) * DIP + k0 + ak;
            #pragma unroll
            for (int j = 0; j < 4; ++j) rZ[j] = *(const float4*)(zg + j * 4);
        }
        const float* bg = W + (size_t)(k0 + bk) * N + n0 + bn;
        #pragma unroll
        for (int j = 0; j < 4; ++j) {
            int col = n0 + bn + j * 4;
            rB[j] = (col < N) ? *(const float4*)(bg + j * 4)
                              : make_float4(0.f, 0.f, 0.f, 0.f);
        }
    };

    auto sts = [&](int buf, int k0) {
        float2* ad = As[buf] + ar * ASF2 + ak;
        #pragma unroll
        for (int j = 0; j < 4; ++j) {
            float v[4] = { rA[j].x, rA[j].y, rA[j].z, rA[j].w };
            if (PRE == 1) {
                const float* wv = prew + k0 + ak + j * 4;
                #pragma unroll
                for (int e = 0; e < 4; ++e) {
                    float x = v[e];
                    row_ss = fmaf(x, x, row_ss);
                    v[e] = x * wv[e];
                }
            } else if (PRE == 2) {
                float zz[4] = { rZ[j].x, rZ[j].y, rZ[j].z, rZ[j].w };
                const float* wv = prew + k0 + ak + j * 4;
                #pragma unroll
                for (int e = 0; e < 4; ++e) {
                    float gg = v[e] * siluf(zz[e]);
                    row_ss = fmaf(gg, gg, row_ss);
                    v[e] = gg * wv[e];
                }
            }
            unsigned h[4], l[4];
            #pragma unroll
            for (int e = 0; e < 4; ++e) tf32_split(v[e], h[e], l[e]);
            uint4* dst = (uint4*)(ad + j * 4);
            dst[0] = make_uint4(h[0], l[0], h[1], l[1]);
            dst[1] = make_uint4(h[2], l[2], h[3], l[3]);
        }
        float2* bd = Bs[buf] + bk * BSF2 + bn;
        #pragma unroll
        for (int j = 0; j < 4; ++j) {
            float v[4] = { rB[j].x, rB[j].y, rB[j].z, rB[j].w };
            unsigned h[4], l[4];
            #pragma unroll
            for (int e = 0; e < 4; ++e) tf32_split(v[e], h[e], l[e]);
            uint4* dst = (uint4*)(bd + j * 4);
            dst[0] = make_uint4(h[0], l[0], h[1], l[1]);
            dst[1] = make_uint4(h[2], l[2], h[3], l[3]);
        }
    };

    int nk = K >> 5;
    loadG(0);
    sts(0, 0);
    loadG(32);
    __syncthreads();

    for (int kb = 0; kb < nk; ++kb) {
        const float2* Ab = As[kb & 1];
        const float2* Bb = Bs[kb & 1];
        #pragma unroll
        for (int ks = 0; ks < 4; ++ks) {
            int kq = ks * 8;
            unsigned ah[2][4], al[2][4];
            #pragma unroll
            for (int mi = 0; mi < 2; ++mi) {
                const float2* ab = Ab + (m0w + mi * 16 + g) * ASF2 + kq + q;
                float2 t0 = ab[0];
                float2 t1 = ab[8 * ASF2];
                float2 t2 = ab[4];
                float2 t3 = ab[8 * ASF2 + 4];
                ah[mi][0] = __float_as_uint(t0.x); al[mi][0] = __float_as_uint(t0.y);
                ah[mi][1] = __float_as_uint(t1.x); al[mi][1] = __float_as_uint(t1.y);
                ah[mi][2] = __float_as_uint(t2.x); al[mi][2] = __float_as_uint(t2.y);
                ah[mi][3] = __float_as_uint(t3.x); al[mi][3] = __float_as_uint(t3.y);
            }
            #pragma unroll
            for (int ni = 0; ni < 8; ++ni) {
                const float2* bb = Bb + (kq + q) * BSF2 + n0w + ni * 8 + g;
                float2 s0 = bb[0];
                float2 s1 = bb[4 * BSF2];
                unsigned bh0 = __float_as_uint(s0.x), bl0 = __float_as_uint(s0.y);
                unsigned bh1 = __float_as_uint(s1.x), bl1 = __float_as_uint(s1.y);
                mma_tf32(acc[0][ni], al[0], bh0, bh1);
                mma_tf32(acc[1][ni], al[1], bh0, bh1);
                mma_tf32(acc[0][ni], ah[0], bl0, bl1);
                mma_tf32(acc[1][ni], ah[1], bl0, bl1);
                mma_tf32(acc[0][ni], ah[0], bh0, bh1);
                mma_tf32(acc[1][ni], ah[1], bh0, bh1);
            }
        }
        if (kb + 1 < nk) {
            __syncthreads();
            sts((kb + 1) & 1, (kb + 1) * 32);
            if (kb + 2 < nk) loadG((kb + 2) * 32);
            __syncthreads();
        }
    }

    if (PRE > 0) {
        float tot = row_ss + __shfl_xor_sync(0xffffffffu, row_ss, 1);
        if ((tid & 1) == 0) s_sc[ar] = rsqrtf(tot * (1.f / (float)K) + 1e-5f);
        __syncthreads();
    }

    #pragma unroll
    for (int mi = 0; mi < 2; ++mi) {
        #pragma unroll
        for (int ni = 0; ni < 8; ++ni) {
            int col = n0 + n0w + ni * 8 + 2 * q;
            if (col >= N) continue;
            #pragma unroll
            for (int half = 0; half < 2; ++half) {
                int lrow = m0w + mi * 16 + g + half * 8;
                int row = m0 + lrow;
                float sc = (PRE > 0) ? s_sc[lrow] : 1.f;
                float v0 = sc * acc[mi][ni][half * 2 + 0];
                float v1 = sc * acc[mi][ni][half * 2 + 1];
                if (EPI == 1) { v0 += bias[col]; v1 += bias[col + 1]; }
                else if (EPI == 2) {
                    v0 += bias[col]; v1 += bias[col + 1];
                    v0 = 0.5f * v0 * (1.f + erff(v0 * 0.70710678118654752f));
                    v1 = 0.5f * v1 * (1.f + erff(v1 * 0.70710678118654752f));
                } else if (EPI == 3) {
                    const float* rp = res + (size_t)row * N + col;
                    v0 += rp[0]; v1 += rp[1];
                }
                *(float2*)(C + (size_t)row * N + col) = make_float2(v0, v1);
            }
        }
    }
}

// ---------------- conv (depthwise causal, DCONV=4) + silu, plus packed dt/dA ----------------
__global__ void __launch_bounds__(256) conv_kernel(
    const float* __restrict__ cw, const float* __restrict__ cb,
    const float* __restrict__ dtb, const float* __restrict__ alog) {
    int r = blockIdx.x;
    int b = r >> 11, t = r & 2047;
    for (int c = threadIdx.x; c < CDIM; c += 256) {
        float acc = cb[c];
        #pragma unroll
        for (int k = 0; k < DCONV; ++k) {
            int tt = t - (DCONV - 1) + k;
            if (tt >= 0)
                acc = fmaf(g_z[((size_t)(b * SEQ + tt)) * DIP + DINNER + c], cw[c * DCONV + k], acc);
        }
        g_xbc[(size_t)r * CDIM + c] = siluf(acc);
    }
    if (threadIdx.x < NHEADS) {
        int hh = threadIdx.x;
        float v = g_z[(size_t)r * DIP + (DIP - NHEADS) + hh] + dtb[hh];
        float dt = (v > 20.f) ? v : log1pf(expf(v));
        float dA = expf(-dt * expf(alog[hh]));
        g_dtA[r * NHEADS + hh] = make_float2(dt, dA);
    }
}

// ---------------- selective scan: warp-autonomous register version (R5, passing) ----------------
#define SDEPTH 4

__global__ void __launch_bounds__(256) scan_kernel(const float* __restrict__ Dp) {
    int pz = blockIdx.x;
    int h  = blockIdx.y;
    int b  = blockIdx.z;
    int tid = threadIdx.x;
    int w = tid >> 5, lane = tid & 31;
    int p_sub = lane >> 3;
    int n_sub = lane & 7;
    int p = pz * 32 + w * 4 + p_sub;

    const float* base = g_xbc + (size_t)b * SEQ * CDIM;
    const float2* dbase = g_dtA + (size_t)b * SEQ * NHEADS + h;
    float* ybase = g_y + (size_t)b * SEQ * DINNER + h * HEADDIM + p;
    float Dv = Dp[h];

    float hs[8];
    #pragma unroll
    for (int j = 0; j < 8; ++j) hs[j] = 0.f;

    float4 Bb[SDEPTH][2], Cb[SDEPTH][2];
    float  xb[SDEPTH];
    float2 db[SDEPTH];

    const int boff = DINNER + n_sub * 8;
    const int coff = DINNER + DSTATE + n_sub * 8;
    const int xoff = h * HEADDIM + p;

    #pragma unroll
    for (int s = 0; s < SDEPTH; ++s) {
        const float* row = base + (size_t)s * CDIM;
        Bb[s][0] = *(const float4*)(row + boff);
        Bb[s][1] = *(const float4*)(row + boff + 4);
        Cb[s][0] = *(const float4*)(row + coff);
        Cb[s][1] = *(const float4*)(row + coff + 4);
        xb[s] = row[xoff];
        db[s] = dbase[(size_t)s * NHEADS];
    }

    for (int t0 = 0; t0 < SEQ; t0 += SDEPTH) {
        #pragma unroll
        for (int s = 0; s < SDEPTH; ++s) {
            int t = t0 + s;
            float dtv = db[s].x, dAv = db[s].y;
            float xv = xb[s];
            float cbm = dtv * xv;
            float4 B0 = Bb[s][0], B1 = Bb[s][1];
            float4 C0 = Cb[s][0], C1 = Cb[s][1];
            float acc;
            hs[0] = fmaf(hs[0], dAv, cbm * B0.x); acc = hs[0] * C0.x;
            hs[1] = fmaf(hs[1], dAv, cbm * B0.y); acc = fmaf(hs[1], C0.y, acc);
            hs[2] = fmaf(hs[2], dAv, cbm * B0.z); acc = fmaf(hs[2], C0.z, acc);
            hs[3] = fmaf(hs[3], dAv, cbm * B0.w); acc = fmaf(hs[3], C0.w, acc);
            hs[4] = fmaf(hs[4], dAv, cbm * B1.x); acc = fmaf(hs[4], C1.x, acc);
            hs[5] = fmaf(hs[5], dAv, cbm * B1.y); acc = fmaf(hs[5], C1.y, acc);
            hs[6] = fmaf(hs[6], dAv, cbm * B1.z); acc = fmaf(hs[6], C1.z, acc);
            hs[7] = fmaf(hs[7], dAv, cbm * B1.w); acc = fmaf(hs[7], C1.w, acc);
            acc += __shfl_xor_sync(0xffffffffu, acc, 1);
            acc += __shfl_xor_sync(0xffffffffu, acc, 2);
            acc += __shfl_xor_sync(0xffffffffu, acc, 4);
            if (n_sub == 0)
                ybase[(size_t)t * DINNER] = acc + Dv * xv;
            int tn = t + SDEPTH;
            if (tn > SEQ - 1) tn = SEQ - 1;
            const float* row = base + (size_t)tn * CDIM;
            Bb[s][0] = *(const float4*)(row + boff);
            Bb[s][1] = *(const float4*)(row + boff + 4);
            Cb[s][0] = *(const float4*)(row + coff);
            Cb[s][1] = *(const float4*)(row + coff + 4);
            xb[s] = row[xoff];
            db[s] = dbase[(size_t)tn * NHEADS];
        }
    }
}

// ---------------- final norms ----------------
__global__ void __launch_bounds__(256) finalnorm_kernel(
    const float* __restrict__ rw, const float* __restrict__ lg, const float* __restrict__ lb) {
    int r = blockIdx.x, e = threadIdx.x;
    float v = g_x[(size_t)r * EMB + e];
    float ss = blockReduceSum(v * v);
    float xr = v * rsqrtf(ss * (1.f / EMB) + 1e-5f) * rw[e];
    float m = blockReduceSum(xr) * (1.f / EMB);
    float d = xr - m;
    float var = blockReduceSum(d * d) * (1.f / EMB);
    g_xn[(size_t)r * EMB + e] = d * rsqrtf(var + 1e-5f) * lg[e] + lb[e];
}

// ---------------- mlp2 ----------------
__global__ void __launch_bounds__(256) mlp2_kernel(
    const float* __restrict__ W2, const float* __restrict__ b2, float* __restrict__ out) {
    __shared__ float Ws[EMB * 5];
    __shared__ float bs[5];
    int tid = threadIdx.x;
    for (int i = tid; i < EMB * 5; i += 256) Ws[i] = W2[i];
    if (tid < 5) bs[tid] = b2[tid];
    __syncthreads();
    int warp = tid >> 5, lane = tid & 31;
    int tok = blockIdx.x * 8 + warp;
    float a0=0,a1=0,a2=0,a3=0,a4=0;
    for (int k = lane; k < EMB; k += 32) {
        float hv = g_h1[(size_t)tok * EMB + k];
        a0 = fmaf(hv, Ws[k * 5 + 0], a0);
        a1 = fmaf(hv, Ws[k * 5 + 1], a1);
        a2 = fmaf(hv, Ws[k * 5 + 2], a2);
        a3 = fmaf(hv, Ws[k * 5 + 3], a3);
        a4 = fmaf(hv, Ws[k * 5 + 4], a4);
    }
    #pragma unroll
    for (int o = 16; o; o >>= 1) {
        a0 += __shfl_xor_sync(0xffffffffu, a0, o);
        a1 += __shfl_xor_sync(0xffffffffu, a1, o);
        a2 += __shfl_xor_sync(0xffffffffu, a2, o);
        a3 += __shfl_xor_sync(0xffffffffu, a3, o);
        a4 += __shfl_xor_sync(0xffffffffu, a4, o);
    }
    if (lane == 0) {
        out[(size_t)tok * 5 + 0] = a0 + bs[0];
        out[(size_t)tok * 5 + 1] = a1 + bs[1];
        out[(size_t)tok * 5 + 2] = a2 + bs[2];
        out[(size_t)tok * 5 + 3] = a3 + bs[3];
        out[(size_t)tok * 5 + 4] = a4 + bs[4];
    }
}

// ---------------- host launcher ----------------
extern "C" void kernel_launch(void* const* d_in, const int* in_sizes, int n_in,
                              void* d_out, int out_size) {
    const float* feature     = (const float*)d_in[0];
    const float* w_avg       = (const float*)d_in[1];
    const float* inproj_ln_g = (const float*)d_in[2];
    const float* inproj_ln_b = (const float*)d_in[3];
    const float* inproj_W    = (const float*)d_in[4];
    const float* inproj_b    = (const float*)d_in[5];
    const float* rms_w       = (const float*)d_in[6];
    const float* m_inW       = (const float*)d_in[7];
    const float* m_convW     = (const float*)d_in[8];
    const float* m_convB     = (const float*)d_in[9];
    const float* m_dtb       = (const float*)d_in[10];
    const float* m_Alog      = (const float*)d_in[11];
    const float* m_D         = (const float*)d_in[12];
    const float* m_gnw       = (const float*)d_in[13];
    const float* m_outW      = (const float*)d_in[14];
    const float* norm_w      = (const float*)d_in[15];
    const float* mlp_ln_g    = (const float*)d_in[16];
    const float* mlp_ln_b    = (const float*)d_in[17];
    const float* mlp_W1      = (const float*)d_in[18];
    const float* mlp_b1      = (const float*)d_in[19];
    const float* mlp_W2      = (const float*)d_in[20];
    const float* mlp_b2      = (const float*)d_in[21];
    float* out = (float*)d_out;

    float *xn, *x, *z, *y, *h1;
    cudaGetSymbolAddress((void**)&xn, g_xn);
    cudaGetSymbolAddress((void**)&x,  g_x);
    cudaGetSymbolAddress((void**)&z,  g_z);
    cudaGetSymbolAddress((void**)&y,  g_y);
    cudaGetSymbolAddress((void**)&h1, g_h1);

    cudaFuncSetAttribute(tgemm2_kernel<0,1>, cudaFuncAttributeMaxDynamicSharedMemorySize, TG2_SMEM);
    cudaFuncSetAttribute(tgemm2_kernel<1,0>, cudaFuncAttributeMaxDynamicSharedMemorySize, TG2_SMEM);
    cudaFuncSetAttribute(tgemm2_kernel<2,3>, cudaFuncAttributeMaxDynamicSharedMemorySize, TG2_SMEM);
    cudaFuncSetAttribute(tgemm2_kernel<0,2>, cudaFuncAttributeMaxDynamicSharedMemorySize, TG2_SMEM);

    softmax_kernel<<<1, 32>>>(w_avg, NFEAT);
    avg_ln_kernel<<<TOK, 128>>>(feature, inproj_ln_g, inproj_ln_b);

    // x = LN(feat_avg) @ inproj_W + inproj_b     (16384x128 @ 128x256)
    tgemm2_kernel<0,1><<<dim3((EMB + 127) / 128, TOK / 128), 256, TG2_SMEM>>>(
        xn, nullptr, inproj_W, nullptr, inproj_b, nullptr, x, TOK, EMB, DMODEL);

    for (int i = 0; i < NLAYERS; ++i) {
        // zxbcdt = rmsnorm(x, rms_w[i]) @ m_inW[i]   (fused pre-norm; 16384x256 @ 256x1160)
        tgemm2_kernel<1,0><<<dim3((DIP + 127) / 128, TOK / 128), 256, TG2_SMEM>>>(
            x, nullptr, m_inW + (size_t)i * EMB * DIP, rms_w + (size_t)i * EMB,
            nullptr, nullptr, z, TOK, DIP, EMB);
        conv_kernel<<<TOK, 256>>>(m_convW + (size_t)i * CDIM * DCONV,
                                  m_convB + (size_t)i * CDIM,
                                  m_dtb + i * NHEADS, m_Alog + i * NHEADS);
        scan_kernel<<<dim3(2, NHEADS, BATCH), 256>>>(m_D + i * NHEADS);
        // x = rmsnorm(y*silu(z), gnw) @ m_outW[i] + x  (fused gate; 16384x512 @ 512x256)
        tgemm2_kernel<2,3><<<dim3((EMB + 127) / 128, TOK / 128), 256, TG2_SMEM>>>(
            y, z, m_outW + (size_t)i * DINNER * EMB, m_gnw + (size_t)i * DINNER,
            nullptr, x, x, TOK, EMB, DINNER);
    }

    finalnorm_kernel<<<TOK, 256>>>(norm_w, mlp_ln_g, mlp_ln_b);
    // h1 = gelu(xn @ W1 + b1)                    (16384x256 @ 256x256)
    tgemm2_kernel<0,2><<<dim3((EMB + 127) / 128, TOK / 128), 256, TG2_SMEM>>>(
        xn, nullptr, mlp_W1, nullptr, mlp_b1, nullptr, h1, TOK, EMB, EMB);
    mlp2_kernel<<<TOK / 8, 256>>>(mlp_W2, mlp_b2, out);
}

// round 13
// speedup vs baseline: 1.2927x; 1.2927x over previous
#include <cuda_runtime.h>
#include <cuda_bf16.h>
#include <math.h>

// ---------------- problem constants ----------------
#define BATCH   8
#define SEQ     2048
#define TOK     (BATCH*SEQ)      // 16384
#define DMODEL  128
#define EMB     256
#define NLAYERS 3
#define NHEADS  8
#define HEADDIM 64
#define DSTATE  64
#define DCONV   4
#define DINNER  (NHEADS*HEADDIM)             // 512
#define DIP     (2*DINNER + 2*DSTATE + NHEADS) // 1160
#define DIPPAD  1280
#define CDIM    (DINNER + 2*DSTATE)          // 640
#define NFEAT   15

// ---------------- device scratch ----------------
__device__ float g_w[16];
__device__ float g_xn[TOK*EMB];
__device__ float g_x [TOK*EMB];
__device__ float g_z [TOK*DIP];
__device__ float g_xbc[TOK*CDIM];
__device__ float2 g_dtA[TOK*NHEADS];   // (.x = dt, .y = dA)
__device__ float g_y [TOK*DINNER];
__device__ float g_h1[TOK*EMB];

// pre-split weight buffers: [n][k/2] u64 = {bf16x2 hi(k0,k1) | bf16x2 lo(k0,k1)}
__device__ unsigned long long g_wt_in  [256*64];          // inproj_W  K=128 N=256
__device__ unsigned long long g_wt_minw[NLAYERS*DIPPAD*128]; // m_inW  K=256 Npad=1280
__device__ unsigned long long g_wt_mout[NLAYERS*256*256]; // m_outW    K=512 N=256
__device__ unsigned long long g_wt_mlp1[256*128];         // mlp_W1    K=256 N=256

// ---------------- helpers ----------------
__device__ __forceinline__ float blockReduceSum(float v) {
    __shared__ float red[32];
    int lane = threadIdx.x & 31;
    int wid  = threadIdx.x >> 5;
    int nw   = (blockDim.x + 31) >> 5;
    #pragma unroll
    for (int o = 16; o; o >>= 1) v += __shfl_xor_sync(0xffffffffu, v, o);
    __syncthreads();
    if (lane == 0) red[wid] = v;
    __syncthreads();
    float tot = 0.f;
    for (int i = 0; i < nw; ++i) tot += red[i];
    return tot;
}

__device__ __forceinline__ float siluf(float x) { return x / (1.f + expf(-x)); }

__device__ __forceinline__ void cp16(void* s, const void* g) {
    unsigned sa = (unsigned)__cvta_generic_to_shared(s);
    asm volatile("cp.async.ca.shared.global [%0], [%1], 16;\n" :: "r"(sa), "l"(g));
}
__device__ __forceinline__ void cp_commit() {
    asm volatile("cp.async.commit_group;\n" ::: "memory");
}
template<int N>
__device__ __forceinline__ void cp_wait() {
    asm volatile("cp.async.wait_group %0;\n" :: "n"(N) : "memory");
}

__device__ __forceinline__ void mma_bf16(float* d, const unsigned* a, unsigned b0, unsigned b1) {
    asm volatile(
        "mma.sync.aligned.m16n8k16.row.col.f32.bf16.bf16.f32 "
        "{%0,%1,%2,%3},{%4,%5,%6,%7},{%8,%9},{%0,%1,%2,%3};\n"
        : "+f"(d[0]), "+f"(d[1]), "+f"(d[2]), "+f"(d[3])
        : "r"(a[0]), "r"(a[1]), "r"(a[2]), "r"(a[3]), "r"(b0), "r"(b1));
}

// exact 2-term bf16 split of a k-pair: hi = truncate(x) (exact), lo = rn_bf16(x - hi)
__device__ __forceinline__ void pack_pair(float v0, float v1, unsigned& hi, unsigned& lo) {
    unsigned u0 = __float_as_uint(v0), u1 = __float_as_uint(v1);
    hi = __byte_perm(u0, u1, 0x7632);            // {lo16 = v0.top16, hi16 = v1.top16}
    float h0 = __uint_as_float(u0 & 0xFFFF0000u);
    float h1 = __uint_as_float(u1 & 0xFFFF0000u);
    asm("cvt.rn.bf16x2.f32 %0, %1, %2;\n" : "=r"(lo) : "f"(v1 - h1), "f"(v0 - h0));
}

// ---------------- weight pre-split/transpose: W[K][N] fp32 -> WT[n][k/2] u64 ----------------
__global__ void __launch_bounds__(256) convw_kernel(
    const float* __restrict__ W, unsigned long long* __restrict__ out,
    int K, int N, int Npad) {
    int i = blockIdx.x * 256 + threadIdx.x;
    int K2 = K >> 1;
    if (i >= Npad * K2) return;
    int n = i / K2, kp = i - n * K2;
    float v0 = 0.f, v1 = 0.f;
    if (n < N) {
        v0 = W[(size_t)(2 * kp) * N + n];
        v1 = W[(size_t)(2 * kp + 1) * N + n];
    }
    unsigned hi, lo;
    pack_pair(v0, v1, hi, lo);
    out[i] = ((unsigned long long)lo << 32) | (unsigned long long)hi;
}

// ---------------- K0: softmax of w_avg ----------------
__global__ void softmax_kernel(const float* __restrict__ wa, int n) {
    if (threadIdx.x == 0) {
        float mx = -1e30f;
        for (int i = 0; i < n; ++i) mx = fmaxf(mx, wa[i]);
        float s = 0.f;
        for (int i = 0; i < n; ++i) { float e = expf(wa[i] - mx); g_w[i] = e; s += e; }
        float inv = 1.f / s;
        for (int i = 0; i < n; ++i) g_w[i] *= inv;
    }
}

// ---------------- K1: weighted feature average + layernorm(128) ----------------
__global__ void __launch_bounds__(128) avg_ln_kernel(
    const float* __restrict__ feat, const float* __restrict__ lg,
    const float* __restrict__ lb) {
    int r = blockIdx.x;
    int d = threadIdx.x;
    float acc = 0.f;
    #pragma unroll
    for (int f = 0; f < NFEAT; ++f)
        acc = fmaf(g_w[f], feat[((size_t)f * TOK + r) * DMODEL + d], acc);
    float m = blockReduceSum(acc) * (1.f / DMODEL);
    float dv = acc - m;
    float var = blockReduceSum(dv * dv) * (1.f / DMODEL);
    g_xn[(size_t)r * DMODEL + d] = dv * rsqrtf(var + 1e-5f) * lg[d] + lb[d];
}

// ---------------- bf16 2-split GEMM: C = epi( sc_row * (pre(A) @ W) ) ----------------
// PRE: 0 plain; 1 rmsnorm fusion; 2 gate fusion. EPI: 0 none; 1 +bias; 2 gelu(x+bias); 3 +res.
// BM=BN=128 BK=32; 8 warps (4m x 2n), warp tile 32x64; smem u64 = {hi-pair, lo-pair}.
#define AQ 20
#define BQ 20
#define A_ST (128*AQ)
#define B_ST (128*BQ)
#define TG3_SMEM ((2*(A_ST + B_ST))*8)   // 81920 bytes

template<int PRE, int EPI>
__global__ void __launch_bounds__(256, 2) tgemm3_kernel(
    const float* __restrict__ A, const float* __restrict__ Az,
    const unsigned long long* __restrict__ WT, const float* __restrict__ prew,
    const float* __restrict__ bias, const float* __restrict__ res,
    float* __restrict__ C, int M, int N, int K)
{
    extern __shared__ unsigned long long sm3[];
    unsigned long long* As[2] = { sm3, sm3 + A_ST };
    unsigned long long* Bs[2] = { sm3 + 2*A_ST, sm3 + 2*A_ST + B_ST };
    __shared__ float s_sc[128];

    int tid = threadIdx.x;
    int n0 = blockIdx.x * 128, m0 = blockIdx.y * 128;
    int wid = tid >> 5, lane = tid & 31;
    int wm = wid >> 1, wn = wid & 1;
    int m0w = wm * 32, n0w = wn * 64;
    int g = lane >> 2, q = lane & 3;

    float acc[2][8][4];
    #pragma unroll
    for (int mi = 0; mi < 2; ++mi)
        #pragma unroll
        for (int ni = 0; ni < 8; ++ni)
            #pragma unroll
            for (int c = 0; c < 4; ++c) acc[mi][ni][c] = 0.f;

    int ar = tid >> 1;                 // A row (2 threads/row)
    int akp = (tid & 1) * 8;           // k-pair offset (0 or 8) -> k offset 0/16
    int K2 = K >> 1;
    int br = tid >> 1;                 // B (n) row
    int bo = (tid & 1) * 8;            // u64 offset within 16-u64 stage row

    float row_ss = 0.f;
    float4 rA[4], rZ[4];

    auto loadA = [&](int kb) {
        const float* ag = A + (size_t)(m0 + ar) * K + kb * 32 + akp * 2;
        #pragma unroll
        for (int j = 0; j < 4; ++j) rA[j] = *(const float4*)(ag + j * 4);
        if (PRE == 2) {
            const float* zg = Az + (size_t)(m0 + ar) * DIP + kb * 32 + akp * 2;
            #pragma unroll
            for (int j = 0; j < 4; ++j) rZ[j] = *(const float4*)(zg + j * 4);
        }
    };

    auto cpB = [&](int buf, int kb) {
        const unsigned long long* src = WT + (size_t)(n0 + br) * K2 + kb * 16 + bo;
        unsigned long long* dst = Bs[buf] + br * BQ + bo;
        cp16(dst + 0, src + 0);
        cp16(dst + 2, src + 2);
        cp16(dst + 4, src + 4);
        cp16(dst + 6, src + 6);
    };

    auto stsA = [&](int buf, int kb) {
        unsigned long long* ad = As[buf] + ar * AQ + akp;
        const float* wv = prew + kb * 32 + akp * 2;
        #pragma unroll
        for (int j = 0; j < 4; ++j) {
            float v[4] = { rA[j].x, rA[j].y, rA[j].z, rA[j].w };
            if (PRE == 1) {
                #pragma unroll
                for (int e = 0; e < 4; ++e) {
                    float x = v[e];
                    row_ss = fmaf(x, x, row_ss);
                    v[e] = x * wv[j * 4 + e];
                }
            } else if (PRE == 2) {
                float zz[4] = { rZ[j].x, rZ[j].y, rZ[j].z, rZ[j].w };
                #pragma unroll
                for (int e = 0; e < 4; ++e) {
                    float gg = v[e] * siluf(zz[e]);
                    row_ss = fmaf(gg, gg, row_ss);
                    v[e] = gg * wv[j * 4 + e];
                }
            }
            unsigned h01, l01, h23, l23;
            pack_pair(v[0], v[1], h01, l01);
            pack_pair(v[2], v[3], h23, l23);
            *(uint4*)(ad + j * 2) = make_uint4(h01, l01, h23, l23);
        }
    };

    auto compute = [&](int buf) {
        const uint2* Au = (const uint2*)As[buf];
        const uint2* Bu = (const uint2*)Bs[buf];
        #pragma unroll
        for (int kk = 0; kk < 2; ++kk) {
            unsigned ah[2][4], al[2][4];
            #pragma unroll
            for (int mi = 0; mi < 2; ++mi) {
                const uint2* ap = Au + (m0w + mi * 16 + g) * AQ + kk * 8 + q;
                uint2 t0 = ap[0];
                uint2 t1 = ap[8 * AQ];
                uint2 t2 = ap[4];
                uint2 t3 = ap[8 * AQ + 4];
                ah[mi][0] = t0.x; al[mi][0] = t0.y;
                ah[mi][1] = t1.x; al[mi][1] = t1.y;
                ah[mi][2] = t2.x; al[mi][2] = t2.y;
                ah[mi][3] = t3.x; al[mi][3] = t3.y;
            }
            #pragma unroll
            for (int ni = 0; ni < 8; ++ni) {
                const uint2* bp = Bu + (n0w + ni * 8 + g) * BQ + kk * 8 + q;
                uint2 s0 = bp[0];
                uint2 s1 = bp[4];
                unsigned bh0 = s0.x, bl0 = s0.y;
                unsigned bh1 = s1.x, bl1 = s1.y;
                mma_bf16(acc[0][ni], al[0], bh0, bh1);
                mma_bf16(acc[1][ni], al[1], bh0, bh1);
                mma_bf16(acc[0][ni], ah[0], bl0, bl1);
                mma_bf16(acc[1][ni], ah[1], bl0, bl1);
                mma_bf16(acc[0][ni], ah[0], bh0, bh1);
                mma_bf16(acc[1][ni], ah[1], bh0, bh1);
            }
        }
    };

    int nk = K >> 5;
    loadA(0);
    cpB(0, 0); cp_commit();
    cpB(1, 1); cp_commit();
    stsA(0, 0);
    loadA(1);

    for (int kb = 0; kb < nk; ++kb) {
        cp_wait<1>();
        __syncthreads();
        compute(kb & 1);
        __syncthreads();
        if (kb + 1 < nk) {
            stsA((kb + 1) & 1, kb + 1);
            if (kb + 2 < nk) {
                loadA(kb + 2);
                cpB((kb + 2) & 1, kb + 2);
            }
        }
        cp_commit();
    }

    if (PRE > 0) {
        float tot = row_ss + __shfl_xor_sync(0xffffffffu, row_ss, 1);
        if ((tid & 1) == 0) s_sc[ar] = rsqrtf(tot * (1.f / (float)K) + 1e-5f);
        __syncthreads();
    }

    #pragma unroll
    for (int mi = 0; mi < 2; ++mi) {
        #pragma unroll
        for (int ni = 0; ni < 8; ++ni) {
            int col = n0 + n0w + ni * 8 + 2 * q;
            if (col >= N) continue;
            #pragma unroll
            for (int half = 0; half < 2; ++half) {
                int lrow = m0w + mi * 16 + g + half * 8;
                int row = m0 + lrow;
                float sc = (PRE > 0) ? s_sc[lrow] : 1.f;
                float v0 = sc * acc[mi][ni][half * 2 + 0];
                float v1 = sc * acc[mi][ni][half * 2 + 1];
                if (EPI == 1) { v0 += bias[col]; v1 += bias[col + 1]; }
                else if (EPI == 2) {
                    v0 += bias[col]; v1 += bias[col + 1];
                    v0 = 0.5f * v0 * (1.f + erff(v0 * 0.70710678118654752f));
                    v1 = 0.5f * v1 * (1.f + erff(v1 * 0.70710678118654752f));
                } else if (EPI == 3) {
                    const float* rp = res + (size_t)row * N + col;
                    v0 += rp[0]; v1 += rp[1];
                }
                *(float2*)(C + (size_t)row * N + col) = make_float2(v0, v1);
            }
        }
    }
}

// ---------------- conv (depthwise causal, DCONV=4) + silu, plus packed dt/dA ----------------
__global__ void __launch_bounds__(256) conv_kernel(
    const float* __restrict__ cw, const float* __restrict__ cb,
    const float* __restrict__ dtb, const float* __restrict__ alog) {
    int r = blockIdx.x;
    int b = r >> 11, t = r & 2047;
    for (int c = threadIdx.x; c < CDIM; c += 256) {
        float acc = cb[c];
        #pragma unroll
        for (int k = 0; k < DCONV; ++k) {
            int tt = t - (DCONV - 1) + k;
            if (tt >= 0)
                acc = fmaf(g_z[((size_t)(b * SEQ + tt)) * DIP + DINNER + c], cw[c * DCONV + k], acc);
        }
        g_xbc[(size_t)r * CDIM + c] = siluf(acc);
    }
    if (threadIdx.x < NHEADS) {
        int hh = threadIdx.x;
        float v = g_z[(size_t)r * DIP + (DIP - NHEADS) + hh] + dtb[hh];
        float dt = (v > 20.f) ? v : log1pf(expf(v));
        float dA = expf(-dt * expf(alog[hh]));
        g_dtA[r * NHEADS + hh] = make_float2(dt, dA);
    }
}

// ---------------- selective scan: warp-autonomous register version ----------------
#define SDEPTH 4

__global__ void __launch_bounds__(256) scan_kernel(const float* __restrict__ Dp) {
    int pz = blockIdx.x;
    int h  = blockIdx.y;
    int b  = blockIdx.z;
    int tid = threadIdx.x;
    int w = tid >> 5, lane = tid & 31;
    int p_sub = lane >> 3;
    int n_sub = lane & 7;
    int p = pz * 32 + w * 4 + p_sub;

    const float* base = g_xbc + (size_t)b * SEQ * CDIM;
    const float2* dbase = g_dtA + (size_t)b * SEQ * NHEADS + h;
    float* ybase = g_y + (size_t)b * SEQ * DINNER + h * HEADDIM + p;
    float Dv = Dp[h];

    float hs[8];
    #pragma unroll
    for (int j = 0; j < 8; ++j) hs[j] = 0.f;

    float4 Bb[SDEPTH][2], Cb[SDEPTH][2];
    float  xb[SDEPTH];
    float2 db[SDEPTH];

    const int boff = DINNER + n_sub * 8;
    const int coff = DINNER + DSTATE + n_sub * 8;
    const int xoff = h * HEADDIM + p;

    #pragma unroll
    for (int s = 0; s < SDEPTH; ++s) {
        const float* row = base + (size_t)s * CDIM;
        Bb[s][0] = *(const float4*)(row + boff);
        Bb[s][1] = *(const float4*)(row + boff + 4);
        Cb[s][0] = *(const float4*)(row + coff);
        Cb[s][1] = *(const float4*)(row + coff + 4);
        xb[s] = row[xoff];
        db[s] = dbase[(size_t)s * NHEADS];
    }

    for (int t0 = 0; t0 < SEQ; t0 += SDEPTH) {
        #pragma unroll
        for (int s = 0; s < SDEPTH; ++s) {
            int t = t0 + s;
            float dtv = db[s].x, dAv = db[s].y;
            float xv = xb[s];
            float cbm = dtv * xv;
            float4 B0 = Bb[s][0], B1 = Bb[s][1];
            float4 C0 = Cb[s][0], C1 = Cb[s][1];
            float acc;
            hs[0] = fmaf(hs[0], dAv, cbm * B0.x); acc = hs[0] * C0.x;
            hs[1] = fmaf(hs[1], dAv, cbm * B0.y); acc = fmaf(hs[1], C0.y, acc);
            hs[2] = fmaf(hs[2], dAv, cbm * B0.z); acc = fmaf(hs[2], C0.z, acc);
            hs[3] = fmaf(hs[3], dAv, cbm * B0.w); acc = fmaf(hs[3], C0.w, acc);
            hs[4] = fmaf(hs[4], dAv, cbm * B1.x); acc = fmaf(hs[4], C1.x, acc);
            hs[5] = fmaf(hs[5], dAv, cbm * B1.y); acc = fmaf(hs[5], C1.y, acc);
            hs[6] = fmaf(hs[6], dAv, cbm * B1.z); acc = fmaf(hs[6], C1.z, acc);
            hs[7] = fmaf(hs[7], dAv, cbm * B1.w); acc = fmaf(hs[7], C1.w, acc);
            acc += __shfl_xor_sync(0xffffffffu, acc, 1);
            acc += __shfl_xor_sync(0xffffffffu, acc, 2);
            acc += __shfl_xor_sync(0xffffffffu, acc, 4);
            if (n_sub == 0)
                ybase[(size_t)t * DINNER] = acc + Dv * xv;
            int tn = t + SDEPTH;
            if (tn > SEQ - 1) tn = SEQ - 1;
            const float* row = base + (size_t)tn * CDIM;
            Bb[s][0] = *(const float4*)(row + boff);
            Bb[s][1] = *(const float4*)(row + boff + 4);
            Cb[s][0] = *(const float4*)(row + coff);
            Cb[s][1] = *(const float4*)(row + coff + 4);
            xb[s] = row[xoff];
            db[s] = dbase[(size_t)tn * NHEADS];
        }
    }
}

// ---------------- final norms ----------------
__global__ void __launch_bounds__(256) finalnorm_kernel(
    const float* __restrict__ rw, const float* __restrict__ lg, const float* __restrict__ lb) {
    int r = blockIdx.x, e = threadIdx.x;
    float v = g_x[(size_t)r * EMB + e];
    float ss = blockReduceSum(v * v);
    float xr = v * rsqrtf(ss * (1.f / EMB) + 1e-5f) * rw[e];
    float m = blockReduceSum(xr) * (1.f / EMB);
    float d = xr - m;
    float var = blockReduceSum(d * d) * (1.f / EMB);
    g_xn[(size_t)r * EMB + e] = d * rsqrtf(var + 1e-5f) * lg[e] + lb[e];
}

// ---------------- mlp2 ----------------
__global__ void __launch_bounds__(256) mlp2_kernel(
    const float* __restrict__ W2, const float* __restrict__ b2, float* __restrict__ out) {
    __shared__ float Ws[EMB * 5];
    __shared__ float bs[5];
    int tid = threadIdx.x;
    for (int i = tid; i < EMB * 5; i += 256) Ws[i] = W2[i];
    if (tid < 5) bs[tid] = b2[tid];
    __syncthreads();
    int warp = tid >> 5, lane = tid & 31;
    int tok = blockIdx.x * 8 + warp;
    float a0=0,a1=0,a2=0,a3=0,a4=0;
    for (int k = lane; k < EMB; k += 32) {
        float hv = g_h1[(size_t)tok * EMB + k];
        a0 = fmaf(hv, Ws[k * 5 + 0], a0);
        a1 = fmaf(hv, Ws[k * 5 + 1], a1);
        a2 = fmaf(hv, Ws[k * 5 + 2], a2);
        a3 = fmaf(hv, Ws[k * 5 + 3], a3);
        a4 = fmaf(hv, Ws[k * 5 + 4], a4);
    }
    #pragma unroll
    for (int o = 16; o; o >>= 1) {
        a0 += __shfl_xor_sync(0xffffffffu, a0, o);
        a1 += __shfl_xor_sync(0xffffffffu, a1, o);
        a2 += __shfl_xor_sync(0xffffffffu, a2, o);
        a3 += __shfl_xor_sync(0xffffffffu, a3, o);
        a4 += __shfl_xor_sync(0xffffffffu, a4, o);
    }
    if (lane == 0) {
        out[(size_t)tok * 5 + 0] = a0 + bs[0];
        out[(size_t)tok * 5 + 1] = a1 + bs[1];
        out[(size_t)tok * 5 + 2] = a2 + bs[2];
        out[(size_t)tok * 5 + 3] = a3 + bs[3];
        out[(size_t)tok * 5 + 4] = a4 + bs[4];
    }
}

// ---------------- host launcher ----------------
extern "C" void kernel_launch(void* const* d_in, const int* in_sizes, int n_in,
                              void* d_out, int out_size) {
    const float* feature     = (const float*)d_in[0];
    const float* w_avg       = (const float*)d_in[1];
    const float* inproj_ln_g = (const float*)d_in[2];
    const float* inproj_ln_b = (const float*)d_in[3];
    const float* inproj_W    = (const float*)d_in[4];
    const float* inproj_b    = (const float*)d_in[5];
    const float* rms_w       = (const float*)d_in[6];
    const float* m_inW       = (const float*)d_in[7];
    const float* m_convW     = (const float*)d_in[8];
    const float* m_convB     = (const float*)d_in[9];
    const float* m_dtb       = (const float*)d_in[10];
    const float* m_Alog      = (const float*)d_in[11];
    const float* m_D         = (const float*)d_in[12];
    const float* m_gnw       = (const float*)d_in[13];
    const float* m_outW      = (const float*)d_in[14];
    const float* norm_w      = (const float*)d_in[15];
    const float* mlp_ln_g    = (const float*)d_in[16];
    const float* mlp_ln_b    = (const float*)d_in[17];
    const float* mlp_W1      = (const float*)d_in[18];
    const float* mlp_b1      = (const float*)d_in[19];
    const float* mlp_W2      = (const float*)d_in[20];
    const float* mlp_b2      = (const float*)d_in[21];
    float* out = (float*)d_out;

    float *xn, *x, *z, *y, *h1;
    unsigned long long *wt_in, *wt_minw, *wt_mout, *wt_mlp1;
    cudaGetSymbolAddress((void**)&xn, g_xn);
    cudaGetSymbolAddress((void**)&x,  g_x);
    cudaGetSymbolAddress((void**)&z,  g_z);
    cudaGetSymbolAddress((void**)&y,  g_y);
    cudaGetSymbolAddress((void**)&h1, g_h1);
    cudaGetSymbolAddress((void**)&wt_in,   g_wt_in);
    cudaGetSymbolAddress((void**)&wt_minw, g_wt_minw);
    cudaGetSymbolAddress((void**)&wt_mout, g_wt_mout);
    cudaGetSymbolAddress((void**)&wt_mlp1, g_wt_mlp1);

    cudaFuncSetAttribute(tgemm3_kernel<0,1>, cudaFuncAttributeMaxDynamicSharedMemorySize, TG3_SMEM);
    cudaFuncSetAttribute(tgemm3_kernel<1,0>, cudaFuncAttributeMaxDynamicSharedMemorySize, TG3_SMEM);
    cudaFuncSetAttribute(tgemm3_kernel<2,3>, cudaFuncAttributeMaxDynamicSharedMemorySize, TG3_SMEM);
    cudaFuncSetAttribute(tgemm3_kernel<0,2>, cudaFuncAttributeMaxDynamicSharedMemorySize, TG3_SMEM);

    // weight pre-split (cheap; runs inside the graph, deterministic)
    convw_kernel<<<64, 256>>>(inproj_W, wt_in, 128, 256, 256);
    for (int i = 0; i < NLAYERS; ++i) {
        convw_kernel<<<640, 256>>>(m_inW + (size_t)i * EMB * DIP,
                                   wt_minw + (size_t)i * DIPPAD * 128, 256, DIP, DIPPAD);
        convw_kernel<<<256, 256>>>(m_outW + (size_t)i * DINNER * EMB,
                                   wt_mout + (size_t)i * 256 * 256, 512, 256, 256);
    }
    convw_kernel<<<128, 256>>>(mlp_W1, wt_mlp1, 256, 256, 256);

    softmax_kernel<<<1, 32>>>(w_avg, NFEAT);
    avg_ln_kernel<<<TOK, 128>>>(feature, inproj_ln_g, inproj_ln_b);

    // x = LN(feat_avg) @ inproj_W + inproj_b     (16384x128 @ 128x256)
    tgemm3_kernel<0,1><<<dim3(2, TOK / 128), 256, TG3_SMEM>>>(
        xn, nullptr, wt_in, nullptr, inproj_b, nullptr, x, TOK, EMB, DMODEL);

    for (int i = 0; i < NLAYERS; ++i) {
        // zxbcdt = rmsnorm(x, rms_w[i]) @ m_inW[i]   (16384x256 @ 256x1160, fused pre-norm)
        tgemm3_kernel<1,0><<<dim3(DIPPAD / 128, TOK / 128), 256, TG3_SMEM>>>(
            x, nullptr, wt_minw + (size_t)i * DIPPAD * 128, rms_w + (size_t)i * EMB,
            nullptr, nullptr, z, TOK, DIP, EMB);
        conv_kernel<<<TOK, 256>>>(m_convW + (size_t)i * CDIM * DCONV,
                                  m_convB + (size_t)i * CDIM,
                                  m_dtb + i * NHEADS, m_Alog + i * NHEADS);
        scan_kernel<<<dim3(2, NHEADS, BATCH), 256>>>(m_D + i * NHEADS);
        // x = rmsnorm(y*silu(z), gnw) @ m_outW[i] + x  (16384x512 @ 512x256, fused gate)
        tgemm3_kernel<2,3><<<dim3(2, TOK / 128), 256, TG3_SMEM>>>(
            y, z, wt_mout + (size_t)i * 256 * 256, m_gnw + (size_t)i * DINNER,
            nullptr, x, x, TOK, EMB, DINNER);
    }

    finalnorm_kernel<<<TOK, 256>>>(norm_w, mlp_ln_g, mlp_ln_b);
    // h1 = gelu(xn @ W1 + b1)                    (16384x256 @ 256x256)
    tgemm3_kernel<0,2><<<dim3(2, TOK / 128), 256, TG3_SMEM>>>(
        xn, nullptr, wt_mlp1, nullptr, mlp_b1, nullptr, h1, TOK, EMB, EMB);
    mlp2_kernel<<<TOK / 8, 256>>>(mlp_W2, mlp_b2, out);
}

// round 14
// speedup vs baseline: 1.4579x; 1.1277x over previous
#include <cuda_runtime.h>
#include <cuda_bf16.h>
#include <math.h>

// ---------------- problem constants ----------------
#define BATCH   8
#define SEQ     2048
#define TOK     (BATCH*SEQ)      // 16384
#define DMODEL  128
#define EMB     256
#define NLAYERS 3
#define NHEADS  8
#define HEADDIM 64
#define DSTATE  64
#define DCONV   4
#define DINNER  (NHEADS*HEADDIM)             // 512
#define DIP     (2*DINNER + 2*DSTATE + NHEADS) // 1160
#define DIPPAD  1280
#define CDIM    (DINNER + 2*DSTATE)          // 640
#define NFEAT   15

// ---------------- device scratch ----------------
__device__ float g_w[16];
__device__ float g_xn[TOK*EMB];
__device__ float g_x [TOK*EMB];
__device__ float g_z [TOK*DIP];
__device__ float g_xbc[TOK*CDIM];
__device__ float2 g_dtA[TOK*NHEADS];   // (.x = dt, .y = dA)
__device__ float g_y [TOK*DINNER];
__device__ float g_h1[TOK*EMB];

// pre-split weight buffers: [n][k/2] u64 = {bf16x2 hi(k0,k1) | bf16x2 lo(k0,k1)}
__device__ unsigned long long g_wt_in  [256*64];          // inproj_W  K=128 N=256
__device__ unsigned long long g_wt_minw[NLAYERS*DIPPAD*128]; // m_inW  K=256 Npad=1280
__device__ unsigned long long g_wt_mout[NLAYERS*256*256]; // m_outW    K=512 N=256
__device__ unsigned long long g_wt_mlp1[256*128];         // mlp_W1    K=256 N=256

// ---------------- helpers ----------------
__device__ __forceinline__ float blockReduceSum(float v) {
    __shared__ float red[32];
    int lane = threadIdx.x & 31;
    int wid  = threadIdx.x >> 5;
    int nw   = (blockDim.x + 31) >> 5;
    #pragma unroll
    for (int o = 16; o; o >>= 1) v += __shfl_xor_sync(0xffffffffu, v, o);
    __syncthreads();
    if (lane == 0) red[wid] = v;
    __syncthreads();
    float tot = 0.f;
    for (int i = 0; i < nw; ++i) tot += red[i];
    return tot;
}

__device__ __forceinline__ float siluf(float x) { return x / (1.f + expf(-x)); }

__device__ __forceinline__ void cp16(void* s, const void* g) {
    unsigned sa = (unsigned)__cvta_generic_to_shared(s);
    asm volatile("cp.async.ca.shared.global [%0], [%1], 16;\n" :: "r"(sa), "l"(g));
}
__device__ __forceinline__ void cp_commit() {
    asm volatile("cp.async.commit_group;\n" ::: "memory");
}
template<int N>
__device__ __forceinline__ void cp_wait() {
    asm volatile("cp.async.wait_group %0;\n" :: "n"(N) : "memory");
}

__device__ __forceinline__ void mma_bf16(float* d, const unsigned* a, unsigned b0, unsigned b1) {
    asm volatile(
        "mma.sync.aligned.m16n8k16.row.col.f32.bf16.bf16.f32 "
        "{%0,%1,%2,%3},{%4,%5,%6,%7},{%8,%9},{%0,%1,%2,%3};\n"
        : "+f"(d[0]), "+f"(d[1]), "+f"(d[2]), "+f"(d[3])
        : "r"(a[0]), "r"(a[1]), "r"(a[2]), "r"(a[3]), "r"(b0), "r"(b1));
}

// exact 2-term bf16 split of a k-pair: hi = truncate(x) (exact), lo = rn_bf16(x - hi)
__device__ __forceinline__ void pack_pair(float v0, float v1, unsigned& hi, unsigned& lo) {
    unsigned u0 = __float_as_uint(v0), u1 = __float_as_uint(v1);
    hi = __byte_perm(u0, u1, 0x7632);            // {lo16 = v0.top16, hi16 = v1.top16}
    float h0 = __uint_as_float(u0 & 0xFFFF0000u);
    float h1 = __uint_as_float(u1 & 0xFFFF0000u);
    asm("cvt.rn.bf16x2.f32 %0, %1, %2;\n" : "=r"(lo) : "f"(v1 - h1), "f"(v0 - h0));
}

// ---------------- weight pre-split/transpose: W[K][N] fp32 -> WT[n][k/2] u64 ----------------
__global__ void __launch_bounds__(256) convw_kernel(
    const float* __restrict__ W, unsigned long long* __restrict__ out,
    int K, int N, int Npad) {
    int i = blockIdx.x * 256 + threadIdx.x;
    int K2 = K >> 1;
    if (i >= Npad * K2) return;
    int n = i / K2, kp = i - n * K2;
    float v0 = 0.f, v1 = 0.f;
    if (n < N) {
        v0 = W[(size_t)(2 * kp) * N + n];
        v1 = W[(size_t)(2 * kp + 1) * N + n];
    }
    unsigned hi, lo;
    pack_pair(v0, v1, hi, lo);
    out[i] = ((unsigned long long)lo << 32) | (unsigned long long)hi;
}

// ---------------- K0: softmax of w_avg ----------------
__global__ void softmax_kernel(const float* __restrict__ wa, int n) {
    if (threadIdx.x == 0) {
        float mx = -1e30f;
        for (int i = 0; i < n; ++i) mx = fmaxf(mx, wa[i]);
        float s = 0.f;
        for (int i = 0; i < n; ++i) { float e = expf(wa[i] - mx); g_w[i] = e; s += e; }
        float inv = 1.f / s;
        for (int i = 0; i < n; ++i) g_w[i] *= inv;
    }
}

// ---------------- K1: weighted feature average + layernorm(128) ----------------
__global__ void __launch_bounds__(128) avg_ln_kernel(
    const float* __restrict__ feat, const float* __restrict__ lg,
    const float* __restrict__ lb) {
    int r = blockIdx.x;
    int d = threadIdx.x;
    float acc = 0.f;
    #pragma unroll
    for (int f = 0; f < NFEAT; ++f)
        acc = fmaf(g_w[f], feat[((size_t)f * TOK + r) * DMODEL + d], acc);
    float m = blockReduceSum(acc) * (1.f / DMODEL);
    float dv = acc - m;
    float var = blockReduceSum(dv * dv) * (1.f / DMODEL);
    g_xn[(size_t)r * DMODEL + d] = dv * rsqrtf(var + 1e-5f) * lg[d] + lb[d];
}

// ---------------- bf16 2-split GEMM: C = epi( sc_row * (pre(A) @ W) ) ----------------
// PRE: 0 plain; 1 rmsnorm fusion; 2 gate fusion. EPI: 0 none; 1 +bias; 2 gelu(x+bias); 3 +res.
// NI: n-tiles per warp (8 -> BN=128, 4 -> BN=64). 8 warps as 4m x 2n, warp tile 32 x NI*8.
#define AQ 20
#define BQ 20
#define A_ST (128*AQ)

template<int PRE, int EPI, int NI>
__global__ void __launch_bounds__(256, 2) tgemm3_kernel(
    const float* __restrict__ A, const float* __restrict__ Az,
    const unsigned long long* __restrict__ WT, const float* __restrict__ prew,
    const float* __restrict__ bias, const float* __restrict__ res,
    float* __restrict__ C, int M, int N, int K)
{
    constexpr int BROWS = NI * 16;            // B rows (n) per tile
    constexpr int B_ST  = BROWS * BQ;
    extern __shared__ unsigned long long sm3[];
    unsigned long long* As[2] = { sm3, sm3 + A_ST };
    unsigned long long* Bs[2] = { sm3 + 2*A_ST, sm3 + 2*A_ST + B_ST };
    __shared__ float s_sc[128];

    int tid = threadIdx.x;
    int n0 = blockIdx.x * BROWS, m0 = blockIdx.y * 128;
    int wid = tid >> 5, lane = tid & 31;
    int wm = wid >> 1, wn = wid & 1;
    int m0w = wm * 32, n0w = wn * (NI * 8);
    int g = lane >> 2, q = lane & 3;

    float acc[2][NI][4];
    #pragma unroll
    for (int mi = 0; mi < 2; ++mi)
        #pragma unroll
        for (int ni = 0; ni < NI; ++ni)
            #pragma unroll
            for (int c = 0; c < 4; ++c) acc[mi][ni][c] = 0.f;

    int ar = tid >> 1;                 // A row (2 threads/row)
    int akp = (tid & 1) * 8;           // k-pair offset (0 or 8) -> k offset 0/16
    int K2 = K >> 1;

    float row_ss = 0.f;
    float4 rA[4], rZ[4];

    auto loadA = [&](int kb) {
        const float* ag = A + (size_t)(m0 + ar) * K + kb * 32 + akp * 2;
        #pragma unroll
        for (int j = 0; j < 4; ++j) rA[j] = *(const float4*)(ag + j * 4);
        if (PRE == 2) {
            const float* zg = Az + (size_t)(m0 + ar) * DIP + kb * 32 + akp * 2;
            #pragma unroll
            for (int j = 0; j < 4; ++j) rZ[j] = *(const float4*)(zg + j * 4);
        }
    };

    auto cpB = [&](int buf, int kb) {
        if (NI == 8) {
            int br = tid >> 1, bo = (tid & 1) * 8;
            const unsigned long long* src = WT + (size_t)(n0 + br) * K2 + kb * 16 + bo;
            unsigned long long* dst = Bs[buf] + br * BQ + bo;
            cp16(dst + 0, src + 0);
            cp16(dst + 2, src + 2);
            cp16(dst + 4, src + 4);
            cp16(dst + 6, src + 6);
        } else {
            int br = tid >> 2, bo = (tid & 3) * 4;
            const unsigned long long* src = WT + (size_t)(n0 + br) * K2 + kb * 16 + bo;
            unsigned long long* dst = Bs[buf] + br * BQ + bo;
            cp16(dst + 0, src + 0);
            cp16(dst + 2, src + 2);
        }
    };

    auto stsA = [&](int buf, int kb) {
        unsigned long long* ad = As[buf] + ar * AQ + akp;
        const float* wv = prew + kb * 32 + akp * 2;
        #pragma unroll
        for (int j = 0; j < 4; ++j) {
            float v[4] = { rA[j].x, rA[j].y, rA[j].z, rA[j].w };
            if (PRE == 1) {
                #pragma unroll
                for (int e = 0; e < 4; ++e) {
                    float x = v[e];
                    row_ss = fmaf(x, x, row_ss);
                    v[e] = x * wv[j * 4 + e];
                }
            } else if (PRE == 2) {
                float zz[4] = { rZ[j].x, rZ[j].y, rZ[j].z, rZ[j].w };
                #pragma unroll
                for (int e = 0; e < 4; ++e) {
                    float gg = v[e] * siluf(zz[e]);
                    row_ss = fmaf(gg, gg, row_ss);
                    v[e] = gg * wv[j * 4 + e];
                }
            }
            unsigned h01, l01, h23, l23;
            pack_pair(v[0], v[1], h01, l01);
            pack_pair(v[2], v[3], h23, l23);
            *(uint4*)(ad + j * 2) = make_uint4(h01, l01, h23, l23);
        }
    };

    auto compute = [&](int buf) {
        const uint2* Au = (const uint2*)As[buf];
        const uint2* Bu = (const uint2*)Bs[buf];
        #pragma unroll
        for (int kk = 0; kk < 2; ++kk) {
            unsigned ah[2][4], al[2][4];
            #pragma unroll
            for (int mi = 0; mi < 2; ++mi) {
                const uint2* ap = Au + (m0w + mi * 16 + g) * AQ + kk * 8 + q;
                uint2 t0 = ap[0];
                uint2 t1 = ap[8 * AQ];
                uint2 t2 = ap[4];
                uint2 t3 = ap[8 * AQ + 4];
                ah[mi][0] = t0.x; al[mi][0] = t0.y;
                ah[mi][1] = t1.x; al[mi][1] = t1.y;
                ah[mi][2] = t2.x; al[mi][2] = t2.y;
                ah[mi][3] = t3.x; al[mi][3] = t3.y;
            }
            #pragma unroll
            for (int ni = 0; ni < NI; ++ni) {
                const uint2* bp = Bu + (n0w + ni * 8 + g) * BQ + kk * 8 + q;
                uint2 s0 = bp[0];
                uint2 s1 = bp[4];
                unsigned bh0 = s0.x, bl0 = s0.y;
                unsigned bh1 = s1.x, bl1 = s1.y;
                mma_bf16(acc[0][ni], al[0], bh0, bh1);
                mma_bf16(acc[1][ni], al[1], bh0, bh1);
                mma_bf16(acc[0][ni], ah[0], bl0, bl1);
                mma_bf16(acc[1][ni], ah[1], bl0, bl1);
                mma_bf16(acc[0][ni], ah[0], bh0, bh1);
                mma_bf16(acc[1][ni], ah[1], bh0, bh1);
            }
        }
    };

    int nk = K >> 5;
    loadA(0);
    cpB(0, 0); cp_commit();
    cpB(1, 1); cp_commit();
    stsA(0, 0);
    loadA(1);

    for (int kb = 0; kb < nk; ++kb) {
        cp_wait<1>();
        __syncthreads();
        compute(kb & 1);
        __syncthreads();
        if (kb + 1 < nk) {
            stsA((kb + 1) & 1, kb + 1);
            if (kb + 2 < nk) {
                loadA(kb + 2);
                cpB((kb + 2) & 1, kb + 2);
            }
        }
        cp_commit();
    }

    if (PRE > 0) {
        float tot = row_ss + __shfl_xor_sync(0xffffffffu, row_ss, 1);
        if ((tid & 1) == 0) s_sc[ar] = rsqrtf(tot * (1.f / (float)K) + 1e-5f);
        __syncthreads();
    }

    #pragma unroll
    for (int mi = 0; mi < 2; ++mi) {
        #pragma unroll
        for (int ni = 0; ni < NI; ++ni) {
            int col = n0 + n0w + ni * 8 + 2 * q;
            if (col >= N) continue;
            #pragma unroll
            for (int half = 0; half < 2; ++half) {
                int lrow = m0w + mi * 16 + g + half * 8;
                int row = m0 + lrow;
                float sc = (PRE > 0) ? s_sc[lrow] : 1.f;
                float v0 = sc * acc[mi][ni][half * 2 + 0];
                float v1 = sc * acc[mi][ni][half * 2 + 1];
                if (EPI == 1) { v0 += bias[col]; v1 += bias[col + 1]; }
                else if (EPI == 2) {
                    v0 += bias[col]; v1 += bias[col + 1];
                    v0 = 0.5f * v0 * (1.f + erff(v0 * 0.70710678118654752f));
                    v1 = 0.5f * v1 * (1.f + erff(v1 * 0.70710678118654752f));
                } else if (EPI == 3) {
                    const float* rp = res + (size_t)row * N + col;
                    v0 += rp[0]; v1 += rp[1];
                }
                *(float2*)(C + (size_t)row * N + col) = make_float2(v0, v1);
            }
        }
    }
}

#define TG3_SMEM_NI8 ((2*A_ST + 2*(128*BQ))*8)
#define TG3_SMEM_NI4 ((2*A_ST + 2*(64*BQ))*8)

// ---------------- conv (depthwise causal, DCONV=4) + silu, plus packed dt/dA ----------------
__global__ void __launch_bounds__(256) conv_kernel(
    const float* __restrict__ cw, const float* __restrict__ cb,
    const float* __restrict__ dtb, const float* __restrict__ alog) {
    int r = blockIdx.x;
    int b = r >> 11, t = r & 2047;
    for (int c = threadIdx.x; c < CDIM; c += 256) {
        float acc = cb[c];
        #pragma unroll
        for (int k = 0; k < DCONV; ++k) {
            int tt = t - (DCONV - 1) + k;
            if (tt >= 0)
                acc = fmaf(g_z[((size_t)(b * SEQ + tt)) * DIP + DINNER + c], cw[c * DCONV + k], acc);
        }
        g_xbc[(size_t)r * CDIM + c] = siluf(acc);
    }
    if (threadIdx.x < NHEADS) {
        int hh = threadIdx.x;
        float v = g_z[(size_t)r * DIP + (DIP - NHEADS) + hh] + dtb[hh];
        float dt = (v > 20.f) ? v : log1pf(expf(v));
        float dA = expf(-dt * expf(alog[hh]));
        g_dtA[r * NHEADS + hh] = make_float2(dt, dA);
    }
}

// ---------------- selective scan: warp-autonomous register version ----------------
#define SDEPTH 8

__global__ void __launch_bounds__(256) scan_kernel(const float* __restrict__ Dp) {
    int pz = blockIdx.x;
    int h  = blockIdx.y;
    int b  = blockIdx.z;
    int tid = threadIdx.x;
    int w = tid >> 5, lane = tid & 31;
    int p_sub = lane >> 3;
    int n_sub = lane & 7;
    int p = pz * 32 + w * 4 + p_sub;

    const float* base = g_xbc + (size_t)b * SEQ * CDIM;
    const float2* dbase = g_dtA + (size_t)b * SEQ * NHEADS + h;
    float* ybase = g_y + (size_t)b * SEQ * DINNER + h * HEADDIM + p;
    float Dv = Dp[h];

    float hs[8];
    #pragma unroll
    for (int j = 0; j < 8; ++j) hs[j] = 0.f;

    float4 Bb[SDEPTH][2], Cb[SDEPTH][2];
    float  xb[SDEPTH];
    float2 db[SDEPTH];

    const int boff = DINNER + n_sub * 8;
    const int coff = DINNER + DSTATE + n_sub * 8;
    const int xoff = h * HEADDIM + p;

    #pragma unroll
    for (int s = 0; s < SDEPTH; ++s) {
        const float* row = base + (size_t)s * CDIM;
        Bb[s][0] = *(const float4*)(row + boff);
        Bb[s][1] = *(const float4*)(row + boff + 4);
        Cb[s][0] = *(const float4*)(row + coff);
        Cb[s][1] = *(const float4*)(row + coff + 4);
        xb[s] = row[xoff];
        db[s] = dbase[(size_t)s * NHEADS];
    }

    for (int t0 = 0; t0 < SEQ; t0 += SDEPTH) {
        #pragma unroll
        for (int s = 0; s < SDEPTH; ++s) {
            int t = t0 + s;
            float dtv = db[s].x, dAv = db[s].y;
            float xv = xb[s];
            float cbm = dtv * xv;
            float4 B0 = Bb[s][0], B1 = Bb[s][1];
            float4 C0 = Cb[s][0], C1 = Cb[s][1];
            float acc;
            hs[0] = fmaf(hs[0], dAv, cbm * B0.x); acc = hs[0] * C0.x;
            hs[1] = fmaf(hs[1], dAv, cbm * B0.y); acc = fmaf(hs[1], C0.y, acc);
            hs[2] = fmaf(hs[2], dAv, cbm * B0.z); acc = fmaf(hs[2], C0.z, acc);
            hs[3] = fmaf(hs[3], dAv, cbm * B0.w); acc = fmaf(hs[3], C0.w, acc);
            hs[4] = fmaf(hs[4], dAv, cbm * B1.x); acc = fmaf(hs[4], C1.x, acc);
            hs[5] = fmaf(hs[5], dAv, cbm * B1.y); acc = fmaf(hs[5], C1.y, acc);
            hs[6] = fmaf(hs[6], dAv, cbm * B1.z); acc = fmaf(hs[6], C1.z, acc);
            hs[7] = fmaf(hs[7], dAv, cbm * B1.w); acc = fmaf(hs[7], C1.w, acc);
            acc += __shfl_xor_sync(0xffffffffu, acc, 1);
            acc += __shfl_xor_sync(0xffffffffu, acc, 2);
            acc += __shfl_xor_sync(0xffffffffu, acc, 4);
            if (n_sub == 0)
                ybase[(size_t)t * DINNER] = acc + Dv * xv;
            int tn = t + SDEPTH;
            if (tn > SEQ - 1) tn = SEQ - 1;
            const float* row = base + (size_t)tn * CDIM;
            Bb[s][0] = *(const float4*)(row + boff);
            Bb[s][1] = *(const float4*)(row + boff + 4);
            Cb[s][0] = *(const float4*)(row + coff);
            Cb[s][1] = *(const float4*)(row + coff + 4);
            xb[s] = row[xoff];
            db[s] = dbase[(size_t)tn * NHEADS];
        }
    }
}

// ---------------- final norms ----------------
__global__ void __launch_bounds__(256) finalnorm_kernel(
    const float* __restrict__ rw, const float* __restrict__ lg, const float* __restrict__ lb) {
    int r = blockIdx.x, e = threadIdx.x;
    float v = g_x[(size_t)r * EMB + e];
    float ss = blockReduceSum(v * v);
    float xr = v * rsqrtf(ss * (1.f / EMB) + 1e-5f) * rw[e];
    float m = blockReduceSum(xr) * (1.f / EMB);
    float d = xr - m;
    float var = blockReduceSum(d * d) * (1.f / EMB);
    g_xn[(size_t)r * EMB + e] = d * rsqrtf(var + 1e-5f) * lg[e] + lb[e];
}

// ---------------- mlp2 ----------------
__global__ void __launch_bounds__(256) mlp2_kernel(
    const float* __restrict__ W2, const float* __restrict__ b2, float* __restrict__ out) {
    __shared__ float Ws[EMB * 5];
    __shared__ float bs[5];
    int tid = threadIdx.x;
    for (int i = tid; i < EMB * 5; i += 256) Ws[i] = W2[i];
    if (tid < 5) bs[tid] = b2[tid];
    __syncthreads();
    int warp = tid >> 5, lane = tid & 31;
    int tok = blockIdx.x * 8 + warp;
    float a0=0,a1=0,a2=0,a3=0,a4=0;
    for (int k = lane; k < EMB; k += 32) {
        float hv = g_h1[(size_t)tok * EMB + k];
        a0 = fmaf(hv, Ws[k * 5 + 0], a0);
        a1 = fmaf(hv, Ws[k * 5 + 1], a1);
        a2 = fmaf(hv, Ws[k * 5 + 2], a2);
        a3 = fmaf(hv, Ws[k * 5 + 3], a3);
        a4 = fmaf(hv, Ws[k * 5 + 4], a4);
    }
    #pragma unroll
    for (int o = 16; o; o >>= 1) {
        a0 += __shfl_xor_sync(0xffffffffu, a0, o);
        a1 += __shfl_xor_sync(0xffffffffu, a1, o);
        a2 += __shfl_xor_sync(0xffffffffu, a2, o);
        a3 += __shfl_xor_sync(0xffffffffu, a3, o);
        a4 += __shfl_xor_sync(0xffffffffu, a4, o);
    }
    if (lane == 0) {
        out[(size_t)tok * 5 + 0] = a0 + bs[0];
        out[(size_t)tok * 5 + 1] = a1 + bs[1];
        out[(size_t)tok * 5 + 2] = a2 + bs[2];
        out[(size_t)tok * 5 + 3] = a3 + bs[3];
        out[(size_t)tok * 5 + 4] = a4 + bs[4];
    }
}

// ---------------- host launcher ----------------
extern "C" void kernel_launch(void* const* d_in, const int* in_sizes, int n_in,
                              void* d_out, int out_size) {
    const float* feature     = (const float*)d_in[0];
    const float* w_avg       = (const float*)d_in[1];
    const float* inproj_ln_g = (const float*)d_in[2];
    const float* inproj_ln_b = (const float*)d_in[3];
    const float* inproj_W    = (const float*)d_in[4];
    const float* inproj_b    = (const float*)d_in[5];
    const float* rms_w       = (const float*)d_in[6];
    const float* m_inW       = (const float*)d_in[7];
    const float* m_convW     = (const float*)d_in[8];
    const float* m_convB     = (const float*)d_in[9];
    const float* m_dtb       = (const float*)d_in[10];
    const float* m_Alog      = (const float*)d_in[11];
    const float* m_D         = (const float*)d_in[12];
    const float* m_gnw       = (const float*)d_in[13];
    const float* m_outW      = (const float*)d_in[14];
    const float* norm_w      = (const float*)d_in[15];
    const float* mlp_ln_g    = (const float*)d_in[16];
    const float* mlp_ln_b    = (const float*)d_in[17];
    const float* mlp_W1      = (const float*)d_in[18];
    const float* mlp_b1      = (const float*)d_in[19];
    const float* mlp_W2      = (const float*)d_in[20];
    const float* mlp_b2      = (const float*)d_in[21];
    float* out = (float*)d_out;

    float *xn, *x, *z, *y, *h1;
    unsigned long long *wt_in, *wt_minw, *wt_mout, *wt_mlp1;
    cudaGetSymbolAddress((void**)&xn, g_xn);
    cudaGetSymbolAddress((void**)&x,  g_x);
    cudaGetSymbolAddress((void**)&z,  g_z);
    cudaGetSymbolAddress((void**)&y,  g_y);
    cudaGetSymbolAddress((void**)&h1, g_h1);
    cudaGetSymbolAddress((void**)&wt_in,   g_wt_in);
    cudaGetSymbolAddress((void**)&wt_minw, g_wt_minw);
    cudaGetSymbolAddress((void**)&wt_mout, g_wt_mout);
    cudaGetSymbolAddress((void**)&wt_mlp1, g_wt_mlp1);

    cudaFuncSetAttribute(tgemm3_kernel<0,1,4>, cudaFuncAttributeMaxDynamicSharedMemorySize, TG3_SMEM_NI4);
    cudaFuncSetAttribute(tgemm3_kernel<1,0,8>, cudaFuncAttributeMaxDynamicSharedMemorySize, TG3_SMEM_NI8);
    cudaFuncSetAttribute(tgemm3_kernel<2,3,4>, cudaFuncAttributeMaxDynamicSharedMemorySize, TG3_SMEM_NI4);
    cudaFuncSetAttribute(tgemm3_kernel<0,2,4>, cudaFuncAttributeMaxDynamicSharedMemorySize, TG3_SMEM_NI4);

    // weight pre-split (cheap; runs inside the graph, deterministic)
    convw_kernel<<<64, 256>>>(inproj_W, wt_in, 128, 256, 256);
    for (int i = 0; i < NLAYERS; ++i) {
        convw_kernel<<<640, 256>>>(m_inW + (size_t)i * EMB * DIP,
                                   wt_minw + (size_t)i * DIPPAD * 128, 256, DIP, DIPPAD);
        convw_kernel<<<256, 256>>>(m_outW + (size_t)i * DINNER * EMB,
                                   wt_mout + (size_t)i * 256 * 256, 512, 256, 256);
    }
    convw_kernel<<<128, 256>>>(mlp_W1, wt_mlp1, 256, 256, 256);

    softmax_kernel<<<1, 32>>>(w_avg, NFEAT);
    avg_ln_kernel<<<TOK, 128>>>(feature, inproj_ln_g, inproj_ln_b);

    // x = LN(feat_avg) @ inproj_W + inproj_b     (16384x128 @ 128x256), BN=64
    tgemm3_kernel<0,1,4><<<dim3(4, TOK / 128), 256, TG3_SMEM_NI4>>>(
        xn, nullptr, wt_in, nullptr, inproj_b, nullptr, x, TOK, EMB, DMODEL);

    for (int i = 0; i < NLAYERS; ++i) {
        // zxbcdt = rmsnorm(x, rms_w[i]) @ m_inW[i]   (16384x256 @ 256x1160), BN=128
        tgemm3_kernel<1,0,8><<<dim3(DIPPAD / 128, TOK / 128), 256, TG3_SMEM_NI8>>>(
            x, nullptr, wt_minw + (size_t)i * DIPPAD * 128, rms_w + (size_t)i * EMB,
            nullptr, nullptr, z, TOK, DIP, EMB);
        conv_kernel<<<TOK, 256>>>(m_convW + (size_t)i * CDIM * DCONV,
                                  m_convB + (size_t)i * CDIM,
                                  m_dtb + i * NHEADS, m_Alog + i * NHEADS);
        scan_kernel<<<dim3(2, NHEADS, BATCH), 256>>>(m_D + i * NHEADS);
        // x = rmsnorm(y*silu(z), gnw) @ m_outW[i] + x  (16384x512 @ 512x256), BN=64
        tgemm3_kernel<2,3,4><<<dim3(4, TOK / 128), 256, TG3_SMEM_NI4>>>(
            y, z, wt_mout + (size_t)i * 256 * 256, m_gnw + (size_t)i * DINNER,
            nullptr, x, x, TOK, EMB, DINNER);
    }

    finalnorm_kernel<<<TOK, 256>>>(norm_w, mlp_ln_g, mlp_ln_b);
    // h1 = gelu(xn @ W1 + b1)                    (16384x256 @ 256x256), BN=64
    tgemm3_kernel<0,2,4><<<dim3(4, TOK / 128), 256, TG3_SMEM_NI4>>>(
        xn, nullptr, wt_mlp1, nullptr, mlp_b1, nullptr, h1, TOK, EMB, EMB);
    mlp2_kernel<<<TOK / 8, 256>>>(mlp_W2, mlp_b2, out);
}

// round 15
// speedup vs baseline: 1.4849x; 1.0185x over previous
#include <cuda_runtime.h>
#include <cuda_bf16.h>
#include <math.h>

// ---------------- problem constants ----------------
#define BATCH   8
#define SEQ     2048
#define TOK     (BATCH*SEQ)      // 16384
#define DMODEL  128
#define EMB     256
#define NLAYERS 3
#define NHEADS  8
#define HEADDIM 64
#define DSTATE  64
#define DCONV   4
#define DINNER  (NHEADS*HEADDIM)             // 512
#define DIP     (2*DINNER + 2*DSTATE + NHEADS) // 1160
#define DIPPAD  1280
#define CDIM    (DINNER + 2*DSTATE)          // 640
#define NFEAT   15

// ---------------- device scratch ----------------
__device__ float g_w[16];
__device__ float g_xn[TOK*EMB];
__device__ float g_x [TOK*EMB];
__device__ float g_z [TOK*DIP];
__device__ float g_xbc[TOK*CDIM];
__device__ float2 g_dtA[TOK*NHEADS];   // (.x = dt, .y = dA)
__device__ float g_y [TOK*DINNER];
__device__ float g_h1[TOK*EMB];

// pre-split weight buffers: [n][k/2] u64 = {bf16x2 hi(k0,k1) | bf16x2 lo(k0,k1)}
__device__ unsigned long long g_wt_in  [256*64];          // inproj_W  K=128 N=256
__device__ unsigned long long g_wt_minw[NLAYERS*DIPPAD*128]; // m_inW  K=256 Npad=1280
__device__ unsigned long long g_wt_mout[NLAYERS*256*256]; // m_outW    K=512 N=256
__device__ unsigned long long g_wt_mlp1[256*128];         // mlp_W1    K=256 N=256

// ---------------- helpers ----------------
__device__ __forceinline__ float blockReduceSum(float v) {
    __shared__ float red[32];
    int lane = threadIdx.x & 31;
    int wid  = threadIdx.x >> 5;
    int nw   = (blockDim.x + 31) >> 5;
    #pragma unroll
    for (int o = 16; o; o >>= 1) v += __shfl_xor_sync(0xffffffffu, v, o);
    __syncthreads();
    if (lane == 0) red[wid] = v;
    __syncthreads();
    float tot = 0.f;
    for (int i = 0; i < nw; ++i) tot += red[i];
    return tot;
}

__device__ __forceinline__ float siluf(float x) { return x / (1.f + expf(-x)); }

__device__ __forceinline__ void cp16(void* s, const void* g) {
    unsigned sa = (unsigned)__cvta_generic_to_shared(s);
    asm volatile("cp.async.ca.shared.global [%0], [%1], 16;\n" :: "r"(sa), "l"(g));
}
__device__ __forceinline__ void cp_commit() {
    asm volatile("cp.async.commit_group;\n" ::: "memory");
}
template<int N>
__device__ __forceinline__ void cp_wait() {
    asm volatile("cp.async.wait_group %0;\n" :: "n"(N) : "memory");
}

__device__ __forceinline__ void mma_bf16(float* d, const unsigned* a, unsigned b0, unsigned b1) {
    asm volatile(
        "mma.sync.aligned.m16n8k16.row.col.f32.bf16.bf16.f32 "
        "{%0,%1,%2,%3},{%4,%5,%6,%7},{%8,%9},{%0,%1,%2,%3};\n"
        : "+f"(d[0]), "+f"(d[1]), "+f"(d[2]), "+f"(d[3])
        : "r"(a[0]), "r"(a[1]), "r"(a[2]), "r"(a[3]), "r"(b0), "r"(b1));
}

// exact 2-term bf16 split of a k-pair: hi = truncate(x) (exact), lo = rn_bf16(x - hi)
__device__ __forceinline__ void pack_pair(float v0, float v1, unsigned& hi, unsigned& lo) {
    unsigned u0 = __float_as_uint(v0), u1 = __float_as_uint(v1);
    hi = __byte_perm(u0, u1, 0x7632);            // {lo16 = v0.top16, hi16 = v1.top16}
    float h0 = __uint_as_float(u0 & 0xFFFF0000u);
    float h1 = __uint_as_float(u1 & 0xFFFF0000u);
    asm("cvt.rn.bf16x2.f32 %0, %1, %2;\n" : "=r"(lo) : "f"(v1 - h1), "f"(v0 - h0));
}

// ---------------- weight pre-split/transpose: W[K][N] fp32 -> WT[n][k/2] u64 ----------------
__global__ void __launch_bounds__(256) convw_kernel(
    const float* __restrict__ W, unsigned long long* __restrict__ out,
    int K, int N, int Npad) {
    int i = blockIdx.x * 256 + threadIdx.x;
    int K2 = K >> 1;
    if (i >= Npad * K2) return;
    int n = i / K2, kp = i - n * K2;
    float v0 = 0.f, v1 = 0.f;
    if (n < N) {
        v0 = W[(size_t)(2 * kp) * N + n];
        v1 = W[(size_t)(2 * kp + 1) * N + n];
    }
    unsigned hi, lo;
    pack_pair(v0, v1, hi, lo);
    out[i] = ((unsigned long long)lo << 32) | (unsigned long long)hi;
}

// ---------------- K0: softmax of w_avg ----------------
__global__ void softmax_kernel(const float* __restrict__ wa, int n) {
    if (threadIdx.x == 0) {
        float mx = -1e30f;
        for (int i = 0; i < n; ++i) mx = fmaxf(mx, wa[i]);
        float s = 0.f;
        for (int i = 0; i < n; ++i) { float e = expf(wa[i] - mx); g_w[i] = e; s += e; }
        float inv = 1.f / s;
        for (int i = 0; i < n; ++i) g_w[i] *= inv;
    }
}

// ---------------- K1: weighted feature average + layernorm(128), warp-per-token ----------------
// grid = TOK/8, 256 threads = 8 warps; each warp: one token, 32 lanes x float4 = 128 dims.
__global__ void __launch_bounds__(256) avg_ln_kernel(
    const float* __restrict__ feat, const float* __restrict__ lg,
    const float* __restrict__ lb) {
    int warp = threadIdx.x >> 5, lane = threadIdx.x & 31;
    int r = blockIdx.x * 8 + warp;
    const float4* fb = (const float4*)feat;
    float4 acc = make_float4(0.f, 0.f, 0.f, 0.f);
    #pragma unroll
    for (int f = 0; f < NFEAT; ++f) {
        float4 v = fb[((size_t)f * TOK + r) * 32 + lane];
        float w = g_w[f];
        acc.x = fmaf(w, v.x, acc.x);
        acc.y = fmaf(w, v.y, acc.y);
        acc.z = fmaf(w, v.z, acc.z);
        acc.w = fmaf(w, v.w, acc.w);
    }
    float s = acc.x + acc.y + acc.z + acc.w;
    #pragma unroll
    for (int o = 16; o; o >>= 1) s += __shfl_xor_sync(0xffffffffu, s, o);
    float m = s * (1.f / DMODEL);
    float dx = acc.x - m, dy = acc.y - m, dz = acc.z - m, dw = acc.w - m;
    float vv = dx * dx + dy * dy + dz * dz + dw * dw;
    #pragma unroll
    for (int o = 16; o; o >>= 1) vv += __shfl_xor_sync(0xffffffffu, vv, o);
    float rs = rsqrtf(vv * (1.f / DMODEL) + 1e-5f);
    float4 G = ((const float4*)lg)[lane];
    float4 Bv = ((const float4*)lb)[lane];
    float4 o;
    o.x = dx * rs * G.x + Bv.x;
    o.y = dy * rs * G.y + Bv.y;
    o.z = dz * rs * G.z + Bv.z;
    o.w = dw * rs * G.w + Bv.w;
    ((float4*)g_xn)[(size_t)r * 32 + lane] = o;
}

// ---------------- bf16 2-split GEMM: C = epi( sc_row * (pre(A) @ W) ) ----------------
// PRE: 0 plain; 1 rmsnorm fusion; 2 gate fusion. EPI: 0 none; 1 +bias; 2 gelu(x+bias); 3 +res.
// NI: n-tiles per warp (8 -> BN=128, 4 -> BN=64). 8 warps as 4m x 2n, warp tile 32 x NI*8.
#define AQ 20
#define BQ 20
#define A_ST (128*AQ)

template<int PRE, int EPI, int NI>
__global__ void __launch_bounds__(256, 2) tgemm3_kernel(
    const float* __restrict__ A, const float* __restrict__ Az,
    const unsigned long long* __restrict__ WT, const float* __restrict__ prew,
    const float* __restrict__ bias, const float* __restrict__ res,
    float* __restrict__ C, int M, int N, int K)
{
    constexpr int BROWS = NI * 16;            // B rows (n) per tile
    constexpr int B_ST  = BROWS * BQ;
    extern __shared__ unsigned long long sm3[];
    unsigned long long* As[2] = { sm3, sm3 + A_ST };
    unsigned long long* Bs[2] = { sm3 + 2*A_ST, sm3 + 2*A_ST + B_ST };
    __shared__ float s_sc[128];

    int tid = threadIdx.x;
    int n0 = blockIdx.x * BROWS, m0 = blockIdx.y * 128;
    int wid = tid >> 5, lane = tid & 31;
    int wm = wid >> 1, wn = wid & 1;
    int m0w = wm * 32, n0w = wn * (NI * 8);
    int g = lane >> 2, q = lane & 3;

    float acc[2][NI][4];
    #pragma unroll
    for (int mi = 0; mi < 2; ++mi)
        #pragma unroll
        for (int ni = 0; ni < NI; ++ni)
            #pragma unroll
            for (int c = 0; c < 4; ++c) acc[mi][ni][c] = 0.f;

    int ar = tid >> 1;                 // A row (2 threads/row)
    int akp = (tid & 1) * 8;           // k-pair offset (0 or 8) -> k offset 0/16
    int K2 = K >> 1;

    float row_ss = 0.f;
    float4 rA[4], rZ[4];

    auto loadA = [&](int kb) {
        const float* ag = A + (size_t)(m0 + ar) * K + kb * 32 + akp * 2;
        #pragma unroll
        for (int j = 0; j < 4; ++j) rA[j] = *(const float4*)(ag + j * 4);
        if (PRE == 2) {
            const float* zg = Az + (size_t)(m0 + ar) * DIP + kb * 32 + akp * 2;
            #pragma unroll
            for (int j = 0; j < 4; ++j) rZ[j] = *(const float4*)(zg + j * 4);
        }
    };

    auto cpB = [&](int buf, int kb) {
        if (NI == 8) {
            int br = tid >> 1, bo = (tid & 1) * 8;
            const unsigned long long* src = WT + (size_t)(n0 + br) * K2 + kb * 16 + bo;
            unsigned long long* dst = Bs[buf] + br * BQ + bo;
            cp16(dst + 0, src + 0);
            cp16(dst + 2, src + 2);
            cp16(dst + 4, src + 4);
            cp16(dst + 6, src + 6);
        } else {
            int br = tid >> 2, bo = (tid & 3) * 4;
            const unsigned long long* src = WT + (size_t)(n0 + br) * K2 + kb * 16 + bo;
            unsigned long long* dst = Bs[buf] + br * BQ + bo;
            cp16(dst + 0, src + 0);
            cp16(dst + 2, src + 2);
        }
    };

    auto stsA = [&](int buf, int kb) {
        unsigned long long* ad = As[buf] + ar * AQ + akp;
        const float* wv = prew + kb * 32 + akp * 2;
        #pragma unroll
        for (int j = 0; j < 4; ++j) {
            float v[4] = { rA[j].x, rA[j].y, rA[j].z, rA[j].w };
            if (PRE == 1) {
                #pragma unroll
                for (int e = 0; e < 4; ++e) {
                    float x = v[e];
                    row_ss = fmaf(x, x, row_ss);
                    v[e] = x * wv[j * 4 + e];
                }
            } else if (PRE == 2) {
                float zz[4] = { rZ[j].x, rZ[j].y, rZ[j].z, rZ[j].w };
                #pragma unroll
                for (int e = 0; e < 4; ++e) {
                    float gg = v[e] * siluf(zz[e]);
                    row_ss = fmaf(gg, gg, row_ss);
                    v[e] = gg * wv[j * 4 + e];
                }
            }
            unsigned h01, l01, h23, l23;
            pack_pair(v[0], v[1], h01, l01);
            pack_pair(v[2], v[3], h23, l23);
            *(uint4*)(ad + j * 2) = make_uint4(h01, l01, h23, l23);
        }
    };

    auto compute = [&](int buf) {
        const uint2* Au = (const uint2*)As[buf];
        const uint2* Bu = (const uint2*)Bs[buf];
        #pragma unroll
        for (int kk = 0; kk < 2; ++kk) {
            unsigned ah[2][4], al[2][4];
            #pragma unroll
            for (int mi = 0; mi < 2; ++mi) {
                const uint2* ap = Au + (m0w + mi * 16 + g) * AQ + kk * 8 + q;
                uint2 t0 = ap[0];
                uint2 t1 = ap[8 * AQ];
                uint2 t2 = ap[4];
                uint2 t3 = ap[8 * AQ + 4];
                ah[mi][0] = t0.x; al[mi][0] = t0.y;
                ah[mi][1] = t1.x; al[mi][1] = t1.y;
                ah[mi][2] = t2.x; al[mi][2] = t2.y;
                ah[mi][3] = t3.x; al[mi][3] = t3.y;
            }
            #pragma unroll
            for (int ni = 0; ni < NI; ++ni) {
                const uint2* bp = Bu + (n0w + ni * 8 + g) * BQ + kk * 8 + q;
                uint2 s0 = bp[0];
                uint2 s1 = bp[4];
                unsigned bh0 = s0.x, bl0 = s0.y;
                unsigned bh1 = s1.x, bl1 = s1.y;
                mma_bf16(acc[0][ni], al[0], bh0, bh1);
                mma_bf16(acc[1][ni], al[1], bh0, bh1);
                mma_bf16(acc[0][ni], ah[0], bl0, bl1);
                mma_bf16(acc[1][ni], ah[1], bl0, bl1);
                mma_bf16(acc[0][ni], ah[0], bh0, bh1);
                mma_bf16(acc[1][ni], ah[1], bh0, bh1);
            }
        }
    };

    int nk = K >> 5;
    loadA(0);
    cpB(0, 0); cp_commit();
    cpB(1, 1); cp_commit();
    stsA(0, 0);
    loadA(1);

    for (int kb = 0; kb < nk; ++kb) {
        cp_wait<1>();
        __syncthreads();
        compute(kb & 1);
        __syncthreads();
        if (kb + 1 < nk) {
            stsA((kb + 1) & 1, kb + 1);
            if (kb + 2 < nk) {
                loadA(kb + 2);
                cpB((kb + 2) & 1, kb + 2);
            }
        }
        cp_commit();
    }

    if (PRE > 0) {
        float tot = row_ss + __shfl_xor_sync(0xffffffffu, row_ss, 1);
        if ((tid & 1) == 0) s_sc[ar] = rsqrtf(tot * (1.f / (float)K) + 1e-5f);
        __syncthreads();
    }

    #pragma unroll
    for (int mi = 0; mi < 2; ++mi) {
        #pragma unroll
        for (int ni = 0; ni < NI; ++ni) {
            int col = n0 + n0w + ni * 8 + 2 * q;
            if (col >= N) continue;
            #pragma unroll
            for (int half = 0; half < 2; ++half) {
                int lrow = m0w + mi * 16 + g + half * 8;
                int row = m0 + lrow;
                float sc = (PRE > 0) ? s_sc[lrow] : 1.f;
                float v0 = sc * acc[mi][ni][half * 2 + 0];
                float v1 = sc * acc[mi][ni][half * 2 + 1];
                if (EPI == 1) { v0 += bias[col]; v1 += bias[col + 1]; }
                else if (EPI == 2) {
                    v0 += bias[col]; v1 += bias[col + 1];
                    v0 = 0.5f * v0 * (1.f + erff(v0 * 0.70710678118654752f));
                    v1 = 0.5f * v1 * (1.f + erff(v1 * 0.70710678118654752f));
                } else if (EPI == 3) {
                    const float* rp = res + (size_t)row * N + col;
                    v0 += rp[0]; v1 += rp[1];
                }
                *(float2*)(C + (size_t)row * N + col) = make_float2(v0, v1);
            }
        }
    }
}

#define TG3_SMEM_NI8 ((2*A_ST + 2*(128*BQ))*8)
#define TG3_SMEM_NI4 ((2*A_ST + 2*(64*BQ))*8)

// ---------------- conv v2: 8-token smem tiles, float4 all the way ----------------
// grid = TOK/8 = 2048, 256 threads. Each block: tokens [t0, t0+8) of batch b.
#define CT 8
__global__ void __launch_bounds__(256) conv_kernel(
    const float* __restrict__ cw, const float* __restrict__ cb,
    const float* __restrict__ dtb, const float* __restrict__ alog) {
    __shared__ float4 sz[CT + 3][160];
    __shared__ float4 scw[CDIM];      // per-channel taps as float4
    __shared__ float  scb[CDIM];
    int tid = threadIdx.x;
    int blk = blockIdx.x;
    int b = blk >> 8;                 // SEQ/CT = 256 tiles per batch
    int t0 = (blk & 255) * CT;

    for (int i = tid; i < CDIM; i += 256) {
        scw[i] = ((const float4*)cw)[i];
        scb[i] = cb[i];
    }
    for (int i = tid; i < (CT + 3) * 160; i += 256) {
        int rr = i / 160, c4 = i - rr * 160;
        int t = t0 - 3 + rr;
        float4 v = make_float4(0.f, 0.f, 0.f, 0.f);
        if (t >= 0)
            v = *(const float4*)(g_z + (size_t)(b * SEQ + t) * DIP + DINNER + c4 * 4);
        sz[rr][c4] = v;
    }
    __syncthreads();

    for (int i = tid; i < CT * 160; i += 256) {
        int s = i / 160, c4 = i - s * 160;
        int c = c4 * 4;
        float4 w0 = scw[c], w1 = scw[c + 1], w2 = scw[c + 2], w3 = scw[c + 3];
        float4 z0 = sz[s][c4], z1 = sz[s + 1][c4], z2 = sz[s + 2][c4], z3 = sz[s + 3][c4];
        float a0 = scb[c    ] + z0.x * w0.x + z1.x * w0.y + z2.x * w0.z + z3.x * w0.w;
        float a1 = scb[c + 1] + z0.y * w1.x + z1.y * w1.y + z2.y * w1.z + z3.y * w1.w;
        float a2 = scb[c + 2] + z0.z * w2.x + z1.z * w2.y + z2.z * w2.z + z3.z * w2.w;
        float a3 = scb[c + 3] + z0.w * w3.x + z1.w * w3.y + z2.w * w3.z + z3.w * w3.w;
        float4 o = make_float4(siluf(a0), siluf(a1), siluf(a2), siluf(a3));
        *(float4*)(g_xbc + (size_t)(b * SEQ + t0 + s) * CDIM + c) = o;
    }

    if (tid < CT * NHEADS) {
        int s = tid >> 3, hh = tid & 7;
        int r = b * SEQ + t0 + s;
        float v = g_z[(size_t)r * DIP + (DIP - NHEADS) + hh] + dtb[hh];
        float dt = (v > 20.f) ? v : log1pf(expf(v));
        float dA = expf(-dt * expf(alog[hh]));
        g_dtA[r * NHEADS + hh] = make_float2(dt, dA);
    }
}

// ---------------- selective scan: warp-autonomous register version ----------------
#define SDEPTH 8

__global__ void __launch_bounds__(256) scan_kernel(const float* __restrict__ Dp) {
    int pz = blockIdx.x;
    int h  = blockIdx.y;
    int b  = blockIdx.z;
    int tid = threadIdx.x;
    int w = tid >> 5, lane = tid & 31;
    int p_sub = lane >> 3;
    int n_sub = lane & 7;
    int p = pz * 32 + w * 4 + p_sub;

    const float* base = g_xbc + (size_t)b * SEQ * CDIM;
    const float2* dbase = g_dtA + (size_t)b * SEQ * NHEADS + h;
    float* ybase = g_y + (size_t)b * SEQ * DINNER + h * HEADDIM + p;
    float Dv = Dp[h];

    float hs[8];
    #pragma unroll
    for (int j = 0; j < 8; ++j) hs[j] = 0.f;

    float4 Bb[SDEPTH][2], Cb[SDEPTH][2];
    float  xb[SDEPTH];
    float2 db[SDEPTH];

    const int boff = DINNER + n_sub * 8;
    const int coff = DINNER + DSTATE + n_sub * 8;
    const int xoff = h * HEADDIM + p;

    #pragma unroll
    for (int s = 0; s < SDEPTH; ++s) {
        const float* row = base + (size_t)s * CDIM;
        Bb[s][0] = *(const float4*)(row + boff);
        Bb[s][1] = *(const float4*)(row + boff + 4);
        Cb[s][0] = *(const float4*)(row + coff);
        Cb[s][1] = *(const float4*)(row + coff + 4);
        xb[s] = row[xoff];
        db[s] = dbase[(size_t)s * NHEADS];
    }

    for (int t0 = 0; t0 < SEQ; t0 += SDEPTH) {
        #pragma unroll
        for (int s = 0; s < SDEPTH; ++s) {
            int t = t0 + s;
            float dtv = db[s].x, dAv = db[s].y;
            float xv = xb[s];
            float cbm = dtv * xv;
            float4 B0 = Bb[s][0], B1 = Bb[s][1];
            float4 C0 = Cb[s][0], C1 = Cb[s][1];
            float acc;
            hs[0] = fmaf(hs[0], dAv, cbm * B0.x); acc = hs[0] * C0.x;
            hs[1] = fmaf(hs[1], dAv, cbm * B0.y); acc = fmaf(hs[1], C0.y, acc);
            hs[2] = fmaf(hs[2], dAv, cbm * B0.z); acc = fmaf(hs[2], C0.z, acc);
            hs[3] = fmaf(hs[3], dAv, cbm * B0.w); acc = fmaf(hs[3], C0.w, acc);
            hs[4] = fmaf(hs[4], dAv, cbm * B1.x); acc = fmaf(hs[4], C1.x, acc);
            hs[5] = fmaf(hs[5], dAv, cbm * B1.y); acc = fmaf(hs[5], C1.y, acc);
            hs[6] = fmaf(hs[6], dAv, cbm * B1.z); acc = fmaf(hs[6], C1.z, acc);
            hs[7] = fmaf(hs[7], dAv, cbm * B1.w); acc = fmaf(hs[7], C1.w, acc);
            acc += __shfl_xor_sync(0xffffffffu, acc, 1);
            acc += __shfl_xor_sync(0xffffffffu, acc, 2);
            acc += __shfl_xor_sync(0xffffffffu, acc, 4);
            if (n_sub == 0)
                ybase[(size_t)t * DINNER] = acc + Dv * xv;
            int tn = t + SDEPTH;
            if (tn > SEQ - 1) tn = SEQ - 1;
            const float* row = base + (size_t)tn * CDIM;
            Bb[s][0] = *(const float4*)(row + boff);
            Bb[s][1] = *(const float4*)(row + boff + 4);
            Cb[s][0] = *(const float4*)(row + coff);
            Cb[s][1] = *(const float4*)(row + coff + 4);
            xb[s] = row[xoff];
            db[s] = dbase[(size_t)tn * NHEADS];
        }
    }
}

// ---------------- final norms ----------------
__global__ void __launch_bounds__(256) finalnorm_kernel(
    const float* __restrict__ rw, const float* __restrict__ lg, const float* __restrict__ lb) {
    int r = blockIdx.x, e = threadIdx.x;
    float v = g_x[(size_t)r * EMB + e];
    float ss = blockReduceSum(v * v);
    float xr = v * rsqrtf(ss * (1.f / EMB) + 1e-5f) * rw[e];
    float m = blockReduceSum(xr) * (1.f / EMB);
    float d = xr - m;
    float var = blockReduceSum(d * d) * (1.f / EMB);
    g_xn[(size_t)r * EMB + e] = d * rsqrtf(var + 1e-5f) * lg[e] + lb[e];
}

// ---------------- mlp2 ----------------
__global__ void __launch_bounds__(256) mlp2_kernel(
    const float* __restrict__ W2, const float* __restrict__ b2, float* __restrict__ out) {
    __shared__ float Ws[EMB * 5];
    __shared__ float bs[5];
    int tid = threadIdx.x;
    for (int i = tid; i < EMB * 5; i += 256) Ws[i] = W2[i];
    if (tid < 5) bs[tid] = b2[tid];
    __syncthreads();
    int warp = tid >> 5, lane = tid & 31;
    int tok = blockIdx.x * 8 + warp;
    float a0=0,a1=0,a2=0,a3=0,a4=0;
    for (int k = lane; k < EMB; k += 32) {
        float hv = g_h1[(size_t)tok * EMB + k];
        a0 = fmaf(hv, Ws[k * 5 + 0], a0);
        a1 = fmaf(hv, Ws[k * 5 + 1], a1);
        a2 = fmaf(hv, Ws[k * 5 + 2], a2);
        a3 = fmaf(hv, Ws[k * 5 + 3], a3);
        a4 = fmaf(hv, Ws[k * 5 + 4], a4);
    }
    #pragma unroll
    for (int o = 16; o; o >>= 1) {
        a0 += __shfl_xor_sync(0xffffffffu, a0, o);
        a1 += __shfl_xor_sync(0xffffffffu, a1, o);
        a2 += __shfl_xor_sync(0xffffffffu, a2, o);
        a3 += __shfl_xor_sync(0xffffffffu, a3, o);
        a4 += __shfl_xor_sync(0xffffffffu, a4, o);
    }
    if (lane == 0) {
        out[(size_t)tok * 5 + 0] = a0 + bs[0];
        out[(size_t)tok * 5 + 1] = a1 + bs[1];
        out[(size_t)tok * 5 + 2] = a2 + bs[2];
        out[(size_t)tok * 5 + 3] = a3 + bs[3];
        out[(size_t)tok * 5 + 4] = a4 + bs[4];
    }
}

// ---------------- host launcher ----------------
extern "C" void kernel_launch(void* const* d_in, const int* in_sizes, int n_in,
                              void* d_out, int out_size) {
    const float* feature     = (const float*)d_in[0];
    const float* w_avg       = (const float*)d_in[1];
    const float* inproj_ln_g = (const float*)d_in[2];
    const float* inproj_ln_b = (const float*)d_in[3];
    const float* inproj_W    = (const float*)d_in[4];
    const float* inproj_b    = (const float*)d_in[5];
    const float* rms_w       = (const float*)d_in[6];
    const float* m_inW       = (const float*)d_in[7];
    const float* m_convW     = (const float*)d_in[8];
    const float* m_convB     = (const float*)d_in[9];
    const float* m_dtb       = (const float*)d_in[10];
    const float* m_Alog      = (const float*)d_in[11];
    const float* m_D         = (const float*)d_in[12];
    const float* m_gnw       = (const float*)d_in[13];
    const float* m_outW      = (const float*)d_in[14];
    const float* norm_w      = (const float*)d_in[15];
    const float* mlp_ln_g    = (const float*)d_in[16];
    const float* mlp_ln_b    = (const float*)d_in[17];
    const float* mlp_W1      = (const float*)d_in[18];
    const float* mlp_b1      = (const float*)d_in[19];
    const float* mlp_W2      = (const float*)d_in[20];
    const float* mlp_b2      = (const float*)d_in[21];
    float* out = (float*)d_out;

    float *xn, *x, *z, *y, *h1;
    unsigned long long *wt_in, *wt_minw, *wt_mout, *wt_mlp1;
    cudaGetSymbolAddress((void**)&xn, g_xn);
    cudaGetSymbolAddress((void**)&x,  g_x);
    cudaGetSymbolAddress((void**)&z,  g_z);
    cudaGetSymbolAddress((void**)&y,  g_y);
    cudaGetSymbolAddress((void**)&h1, g_h1);
    cudaGetSymbolAddress((void**)&wt_in,   g_wt_in);
    cudaGetSymbolAddress((void**)&wt_minw, g_wt_minw);
    cudaGetSymbolAddress((void**)&wt_mout, g_wt_mout);
    cudaGetSymbolAddress((void**)&wt_mlp1, g_wt_mlp1);

    cudaFuncSetAttribute(tgemm3_kernel<0,1,4>, cudaFuncAttributeMaxDynamicSharedMemorySize, TG3_SMEM_NI4);
    cudaFuncSetAttribute(tgemm3_kernel<1,0,8>, cudaFuncAttributeMaxDynamicSharedMemorySize, TG3_SMEM_NI8);
    cudaFuncSetAttribute(tgemm3_kernel<2,3,4>, cudaFuncAttributeMaxDynamicSharedMemorySize, TG3_SMEM_NI4);
    cudaFuncSetAttribute(tgemm3_kernel<0,2,4>, cudaFuncAttributeMaxDynamicSharedMemorySize, TG3_SMEM_NI4);

    // launches 0-5 ordered so ncu (-s 5 -c 1) captures the big inproj GEMM
    convw_kernel<<<64, 256>>>(inproj_W, wt_in, 128, 256, 256);                      // 0
    convw_kernel<<<640, 256>>>(m_inW, wt_minw, 256, DIP, DIPPAD);                   // 1 (layer 0)
    softmax_kernel<<<1, 32>>>(w_avg, NFEAT);                                        // 2
    avg_ln_kernel<<<TOK / 8, 256>>>(feature, inproj_ln_g, inproj_ln_b);             // 3
    // x = LN(feat_avg) @ inproj_W + inproj_b     (16384x128 @ 128x256), BN=64
    tgemm3_kernel<0,1,4><<<dim3(4, TOK / 128), 256, TG3_SMEM_NI4>>>(
        xn, nullptr, wt_in, nullptr, inproj_b, nullptr, x, TOK, EMB, DMODEL);       // 4
    // layer-0 inproj GEMM at launch index 5 — ncu capture target
    tgemm3_kernel<1,0,8><<<dim3(DIPPAD / 128, TOK / 128), 256, TG3_SMEM_NI8>>>(
        x, nullptr, wt_minw, rms_w, nullptr, nullptr, z, TOK, DIP, EMB);            // 5

    // remaining weight pre-splits
    for (int i = 1; i < NLAYERS; ++i)
        convw_kernel<<<640, 256>>>(m_inW + (size_t)i * EMB * DIP,
                                   wt_minw + (size_t)i * DIPPAD * 128, 256, DIP, DIPPAD);
    for (int i = 0; i < NLAYERS; ++i)
        convw_kernel<<<256, 256>>>(m_outW + (size_t)i * DINNER * EMB,
                                   wt_mout + (size_t)i * 256 * 256, 512, 256, 256);
    convw_kernel<<<128, 256>>>(mlp_W1, wt_mlp1, 256, 256, 256);

    for (int i = 0; i < NLAYERS; ++i) {
        if (i > 0) {
            // zxbcdt = rmsnorm(x, rms_w[i]) @ m_inW[i]   (16384x256 @ 256x1160), BN=128
            tgemm3_kernel<1,0,8><<<dim3(DIPPAD / 128, TOK / 128), 256, TG3_SMEM_NI8>>>(
                x, nullptr, wt_minw + (size_t)i * DIPPAD * 128, rms_w + (size_t)i * EMB,
                nullptr, nullptr, z, TOK, DIP, EMB);
        }
        conv_kernel<<<TOK / CT, 256>>>(m_convW + (size_t)i * CDIM * DCONV,
                                       m_convB + (size_t)i * CDIM,
                                       m_dtb + i * NHEADS, m_Alog + i * NHEADS);
        scan_kernel<<<dim3(2, NHEADS, BATCH), 256>>>(m_D + i * NHEADS);
        // x = rmsnorm(y*silu(z), gnw) @ m_outW[i] + x  (16384x512 @ 512x256), BN=64
        tgemm3_kernel<2,3,4><<<dim3(4, TOK / 128), 256, TG3_SMEM_NI4>>>(
            y, z, wt_mout + (size_t)i * 256 * 256, m_gnw + (size_t)i * DINNER,
            nullptr, x, x, TOK, EMB, DINNER);
    }

    finalnorm_kernel<<<TOK, 256>>>(norm_w, mlp_ln_g, mlp_ln_b);
    // h1 = gelu(xn @ W1 + b1)                    (16384x256 @ 256x256), BN=64
    tgemm3_kernel<0,2,4><<<dim3(4, TOK / 128), 256, TG3_SMEM_NI4>>>(
        xn, nullptr, wt_mlp1, nullptr, mlp_b1, nullptr, h1, TOK, EMB, EMB);
    mlp2_kernel<<<TOK / 8, 256>>>(mlp_W2, mlp_b2, out);
}

// round 17
// speedup vs baseline: 1.5818x; 1.0653x over previous
#include <cuda_runtime.h>
#include <cuda_bf16.h>
#include <math.h>

// ---------------- problem constants ----------------
#define BATCH   8
#define SEQ     2048
#define TOK     (BATCH*SEQ)      // 16384
#define DMODEL  128
#define EMB     256
#define NLAYERS 3
#define NHEADS  8
#define HEADDIM 64
#define DSTATE  64
#define DCONV   4
#define DINNER  (NHEADS*HEADDIM)             // 512
#define DIP     (2*DINNER + 2*DSTATE + NHEADS) // 1160
#define DIPPAD  1280
#define CDIM    (DINNER + 2*DSTATE)          // 640
#define NFEAT   15

// ---------------- device scratch ----------------
__device__ float g_w[16];
__device__ float g_x [TOK*EMB];
__device__ float g_z [TOK*DIP];
__device__ float g_xbc[TOK*CDIM];
__device__ float2 g_dtA[TOK*NHEADS];
__device__ float g_y [TOK*DINNER];
__device__ float g_h1[TOK*EMB];

// packed activations: u64 = bf16x2(hi k0,k1) | bf16x2(lo k0,k1)<<32 ; max K=512 -> 256 u64/row
__device__ unsigned long long g_apk[TOK*256];
__device__ float g_ascale[TOK];

// pre-split weights: [n][k/2] u64
__device__ unsigned long long g_wt_in  [256*64];
__device__ unsigned long long g_wt_minw[NLAYERS*DIPPAD*128];
__device__ unsigned long long g_wt_mout[NLAYERS*256*256];
__device__ unsigned long long g_wt_mlp1[256*128];

// ---------------- helpers ----------------
__device__ __forceinline__ float siluf(float x) { return x / (1.f + expf(-x)); }

__device__ __forceinline__ void cp16(void* s, const void* g) {
    unsigned sa = (unsigned)__cvta_generic_to_shared(s);
    asm volatile("cp.async.ca.shared.global [%0], [%1], 16;\n" :: "r"(sa), "l"(g));
}
__device__ __forceinline__ void cp_commit() {
    asm volatile("cp.async.commit_group;\n" ::: "memory");
}
template<int N>
__device__ __forceinline__ void cp_wait() {
    asm volatile("cp.async.wait_group %0;\n" :: "n"(N) : "memory");
}

__device__ __forceinline__ void mma_bf16(float* d, const unsigned* a, unsigned b0, unsigned b1) {
    asm volatile(
        "mma.sync.aligned.m16n8k16.row.col.f32.bf16.bf16.f32 "
        "{%0,%1,%2,%3},{%4,%5,%6,%7},{%8,%9},{%0,%1,%2,%3};\n"
        : "+f"(d[0]), "+f"(d[1]), "+f"(d[2]), "+f"(d[3])
        : "r"(a[0]), "r"(a[1]), "r"(a[2]), "r"(a[3]), "r"(b0), "r"(b1));
}

// exact 2-term bf16 split of a k-pair: hi = truncate (exact), lo = rn_bf16(residual)
__device__ __forceinline__ void pack_pair(float v0, float v1, unsigned& hi, unsigned& lo) {
    unsigned u0 = __float_as_uint(v0), u1 = __float_as_uint(v1);
    hi = __byte_perm(u0, u1, 0x7632);
    float h0 = __uint_as_float(u0 & 0xFFFF0000u);
    float h1 = __uint_as_float(u1 & 0xFFFF0000u);
    asm("cvt.rn.bf16x2.f32 %0, %1, %2;\n" : "=r"(lo) : "f"(v1 - h1), "f"(v0 - h0));
}
__device__ __forceinline__ unsigned long long pk64(float v0, float v1) {
    unsigned hi, lo;
    pack_pair(v0, v1, hi, lo);
    return ((unsigned long long)lo << 32) | (unsigned long long)hi;
}
__device__ __forceinline__ float warpRed(float v) {
    #pragma unroll
    for (int o = 16; o; o >>= 1) v += __shfl_xor_sync(0xffffffffu, v, o);
    return v;
}

// ---------------- weight pre-split/transpose ----------------
__global__ void __launch_bounds__(256) convw_kernel(
    const float* __restrict__ W, unsigned long long* __restrict__ out,
    int K, int N, int Npad) {
    int i = blockIdx.x * 256 + threadIdx.x;
    int K2 = K >> 1;
    if (i >= Npad * K2) return;
    int n = i / K2, kp = i - n * K2;
    float v0 = 0.f, v1 = 0.f;
    if (n < N) {
        v0 = W[(size_t)(2 * kp) * N + n];
        v1 = W[(size_t)(2 * kp + 1) * N + n];
    }
    out[i] = pk64(v0, v1);
}

// ---------------- K0: softmax of w_avg ----------------
__global__ void softmax_kernel(const float* __restrict__ wa, int n) {
    if (threadIdx.x == 0) {
        float mx = -1e30f;
        for (int i = 0; i < n; ++i) mx = fmaxf(mx, wa[i]);
        float s = 0.f;
        for (int i = 0; i < n; ++i) { float e = expf(wa[i] - mx); g_w[i] = e; s += e; }
        float inv = 1.f / s;
        for (int i = 0; i < n; ++i) g_w[i] *= inv;
    }
}

// ---------------- K1: feature average + layernorm(128), packs A directly ----------------
__global__ void __launch_bounds__(256) avg_ln_kernel(
    const float* __restrict__ feat, const float* __restrict__ lg,
    const float* __restrict__ lb, unsigned long long* __restrict__ apk) {
    int warp = threadIdx.x >> 5, lane = threadIdx.x & 31;
    int r = blockIdx.x * 8 + warp;
    const float4* fb = (const float4*)feat;
    float4 acc = make_float4(0.f, 0.f, 0.f, 0.f);
    #pragma unroll
    for (int f = 0; f < NFEAT; ++f) {
        float4 v = fb[((size_t)f * TOK + r) * 32 + lane];
        float w = g_w[f];
        acc.x = fmaf(w, v.x, acc.x);
        acc.y = fmaf(w, v.y, acc.y);
        acc.z = fmaf(w, v.z, acc.z);
        acc.w = fmaf(w, v.w, acc.w);
    }
    float m = warpRed(acc.x + acc.y + acc.z + acc.w) * (1.f / DMODEL);
    float dx = acc.x - m, dy = acc.y - m, dz = acc.z - m, dw = acc.w - m;
    float vv = warpRed(dx * dx + dy * dy + dz * dz + dw * dw);
    float rs = rsqrtf(vv * (1.f / DMODEL) + 1e-5f);
    float4 G = ((const float4*)lg)[lane];
    float4 Bv = ((const float4*)lb)[lane];
    float o0 = dx * rs * G.x + Bv.x;
    float o1 = dy * rs * G.y + Bv.y;
    float o2 = dz * rs * G.z + Bv.z;
    float o3 = dw * rs * G.w + Bv.w;
    unsigned long long* dst = apk + (size_t)r * 64 + lane * 2;
    dst[0] = pk64(o0, o1);
    dst[1] = pk64(o2, o3);
}

// ---------------- pack_rms: apk = pack(x * rw), scale = rsqrt(mean x^2) ----------------
__global__ void __launch_bounds__(256) pack_rms_kernel(
    const float* __restrict__ X, const float* __restrict__ rw,
    unsigned long long* __restrict__ apk, float* __restrict__ scale) {
    int warp = threadIdx.x >> 5, lane = threadIdx.x & 31;
    int r = blockIdx.x * 8 + warp;
    const float4* xr = (const float4*)(X + (size_t)r * EMB);
    float4 a = xr[lane * 2], b = xr[lane * 2 + 1];
    float ss = a.x*a.x + a.y*a.y + a.z*a.z + a.w*a.w
             + b.x*b.x + b.y*b.y + b.z*b.z + b.w*b.w;
    ss = warpRed(ss);
    if (lane == 0) scale[r] = rsqrtf(ss * (1.f / EMB) + 1e-5f);
    const float4* w4 = (const float4*)rw;
    float4 wa = w4[lane * 2], wb = w4[lane * 2 + 1];
    unsigned long long* dst = apk + (size_t)r * 128 + lane * 4;
    dst[0] = pk64(a.x * wa.x, a.y * wa.y);
    dst[1] = pk64(a.z * wa.z, a.w * wa.w);
    dst[2] = pk64(b.x * wb.x, b.y * wb.y);
    dst[3] = pk64(b.z * wb.z, b.w * wb.w);
}

// ---------------- pack_gate: g = y*silu(z); apk = pack(g*gnw), scale ----------------
__global__ void __launch_bounds__(256) pack_gate_kernel(
    const float* __restrict__ gnw,
    unsigned long long* __restrict__ apk, float* __restrict__ scale) {
    int warp = threadIdx.x >> 5, lane = threadIdx.x & 31;
    int r = blockIdx.x * 8 + warp;
    const float4* yr = (const float4*)(g_y + (size_t)r * DINNER);
    const float4* zr = (const float4*)(g_z + (size_t)r * DIP);
    const float4* w4 = (const float4*)gnw;
    float gv[16];
    float ss = 0.f;
    #pragma unroll
    for (int j = 0; j < 4; ++j) {
        float4 yv = yr[lane * 4 + j];
        float4 zv = zr[lane * 4 + j];
        float g0 = yv.x * siluf(zv.x);
        float g1 = yv.y * siluf(zv.y);
        float g2 = yv.z * siluf(zv.z);
        float g3 = yv.w * siluf(zv.w);
        ss += g0*g0 + g1*g1 + g2*g2 + g3*g3;
        gv[j*4+0] = g0; gv[j*4+1] = g1; gv[j*4+2] = g2; gv[j*4+3] = g3;
    }
    ss = warpRed(ss);
    if (lane == 0) scale[r] = rsqrtf(ss * (1.f / DINNER) + 1e-5f);
    unsigned long long* dst = apk + (size_t)r * 256 + lane * 8;
    #pragma unroll
    for (int j = 0; j < 4; ++j) {
        float4 wv = w4[lane * 4 + j];
        dst[j*2 + 0] = pk64(gv[j*4+0] * wv.x, gv[j*4+1] * wv.y);
        dst[j*2 + 1] = pk64(gv[j*4+2] * wv.z, gv[j*4+3] * wv.w);
    }
}

// ---------------- finalnorm_pack: rmsnorm then layernorm, packed output ----------------
__global__ void __launch_bounds__(256) finalnorm_kernel(
    const float* __restrict__ rw, const float* __restrict__ lg,
    const float* __restrict__ lb, unsigned long long* __restrict__ apk) {
    int warp = threadIdx.x >> 5, lane = threadIdx.x & 31;
    int r = blockIdx.x * 8 + warp;
    const float4* xr = (const float4*)(g_x + (size_t)r * EMB);
    float4 a = xr[lane * 2], b = xr[lane * 2 + 1];
    float ss = a.x*a.x + a.y*a.y + a.z*a.z + a.w*a.w
             + b.x*b.x + b.y*b.y + b.z*b.z + b.w*b.w;
    ss = warpRed(ss);
    float rs = rsqrtf(ss * (1.f / EMB) + 1e-5f);
    const float4* w4 = (const float4*)rw;
    float4 wa = w4[lane * 2], wb = w4[lane * 2 + 1];
    float x0 = a.x * rs * wa.x, x1 = a.y * rs * wa.y, x2 = a.z * rs * wa.z, x3 = a.w * rs * wa.w;
    float x4 = b.x * rs * wb.x, x5 = b.y * rs * wb.y, x6 = b.z * rs * wb.z, x7 = b.w * rs * wb.w;
    float m = warpRed(x0+x1+x2+x3+x4+x5+x6+x7) * (1.f / EMB);
    float d0=x0-m, d1=x1-m, d2=x2-m, d3=x3-m, d4=x4-m, d5=x5-m, d6=x6-m, d7=x7-m;
    float var = warpRed(d0*d0+d1*d1+d2*d2+d3*d3+d4*d4+d5*d5+d6*d6+d7*d7) * (1.f / EMB);
    float rv = rsqrtf(var + 1e-5f);
    const float4* g4 = (const float4*)lg;
    const float4* b4 = (const float4*)lb;
    float4 ga = g4[lane * 2], gb = g4[lane * 2 + 1];
    float4 ba = b4[lane * 2], bb = b4[lane * 2 + 1];
    unsigned long long* dst = apk + (size_t)r * 128 + lane * 4;
    dst[0] = pk64(d0 * rv * ga.x + ba.x, d1 * rv * ga.y + ba.y);
    dst[1] = pk64(d2 * rv * ga.z + ba.z, d3 * rv * ga.w + ba.w);
    dst[2] = pk64(d4 * rv * gb.x + bb.x, d5 * rv * gb.y + bb.y);
    dst[3] = pk64(d6 * rv * gb.z + bb.z, d7 * rv * gb.w + bb.w);
}

// ---------------- tgemm4: both operands packed u64, pure cp.async ----------------
// EPI: 0 none; 1 +bias; 2 gelu(x+bias); 3 +residual.  HAS_SC: multiply row scale.
// NI=8: BN=128, 2 stages, 2 syncs/kb. NI=4: BN=64, 3 stages, 1 sync/kb.
#define AQ 20
#define BQ 20
#define A_ST (128*AQ)

template<int EPI, int NI, int HAS_SC>
__global__ void __launch_bounds__(256, 2) tgemm4_kernel(
    const unsigned long long* __restrict__ Apk, const float* __restrict__ scaleA,
    const unsigned long long* __restrict__ WT,
    const float* __restrict__ bias, const float* __restrict__ res,
    float* __restrict__ C, int M, int N, int K)
{
    constexpr int BROWS = NI * 16;
    constexpr int B_ST  = BROWS * BQ;
    constexpr int STAGES = (NI == 8) ? 2 : 3;
    extern __shared__ unsigned long long sm4[];
    unsigned long long* As[3];
    unsigned long long* Bs[3];
    #pragma unroll
    for (int s = 0; s < STAGES; ++s) {
        As[s] = sm4 + s * A_ST;
        Bs[s] = sm4 + STAGES * A_ST + s * B_ST;
    }

    int tid = threadIdx.x;
    int n0 = blockIdx.x * BROWS, m0 = blockIdx.y * 128;
    int wid = tid >> 5, lane = tid & 31;
    int wm = wid >> 1, wn = wid & 1;
    int m0w = wm * 32, n0w = wn * (NI * 8);
    int g = lane >> 2, q = lane & 3;
    int K2 = K >> 1;

    float acc[2][NI][4];
    #pragma unroll
    for (int mi = 0; mi < 2; ++mi)
        #pragma unroll
        for (int ni = 0; ni < NI; ++ni)
            #pragma unroll
            for (int c = 0; c < 4; ++c) acc[mi][ni][c] = 0.f;

    auto cpA = [&](int buf, int kb) {
        int row = tid >> 1, off = (tid & 1) * 8;
        const unsigned long long* src = Apk + (size_t)(m0 + row) * K2 + kb * 16 + off;
        unsigned long long* dst = As[buf] + row * AQ + off;
        cp16(dst + 0, src + 0);
        cp16(dst + 2, src + 2);
        cp16(dst + 4, src + 4);
        cp16(dst + 6, src + 6);
    };
    auto cpB = [&](int buf, int kb) {
        if (NI == 8) {
            int br = tid >> 1, bo = (tid & 1) * 8;
            const unsigned long long* src = WT + (size_t)(n0 + br) * K2 + kb * 16 + bo;
            unsigned long long* dst = Bs[buf] + br * BQ + bo;
            cp16(dst + 0, src + 0);
            cp16(dst + 2, src + 2);
            cp16(dst + 4, src + 4);
            cp16(dst + 6, src + 6);
        } else {
            int br = tid >> 2, bo = (tid & 3) * 4;
            const unsigned long long* src = WT + (size_t)(n0 + br) * K2 + kb * 16 + bo;
            unsigned long long* dst = Bs[buf] + br * BQ + bo;
            cp16(dst + 0, src + 0);
            cp16(dst + 2, src + 2);
        }
    };

    auto compute = [&](int buf) {
        const uint2* Au = (const uint2*)As[buf];
        const uint2* Bu = (const uint2*)Bs[buf];
        #pragma unroll
        for (int kk = 0; kk < 2; ++kk) {
            unsigned ah[2][4], al[2][4];
            #pragma unroll
            for (int mi = 0; mi < 2; ++mi) {
                const uint2* ap = Au + (m0w + mi * 16 + g) * AQ + kk * 8 + q;
                uint2 t0 = ap[0];
                uint2 t1 = ap[8 * AQ];
                uint2 t2 = ap[4];
                uint2 t3 = ap[8 * AQ + 4];
                ah[mi][0] = t0.x; al[mi][0] = t0.y;
                ah[mi][1] = t1.x; al[mi][1] = t1.y;
                ah[mi][2] = t2.x; al[mi][2] = t2.y;
                ah[mi][3] = t3.x; al[mi][3] = t3.y;
            }
            #pragma unroll
            for (int ni = 0; ni < NI; ++ni) {
                const uint2* bp = Bu + (n0w + ni * 8 + g) * BQ + kk * 8 + q;
                uint2 s0 = bp[0];
                uint2 s1 = bp[4];
                mma_bf16(acc[0][ni], al[0], s0.x, s1.x);
                mma_bf16(acc[1][ni], al[1], s0.x, s1.x);
                mma_bf16(acc[0][ni], ah[0], s0.y, s1.y);
                mma_bf16(acc[1][ni], ah[1], s0.y, s1.y);
                mma_bf16(acc[0][ni], ah[0], s0.x, s1.x);
                mma_bf16(acc[1][ni], ah[1], s0.x, s1.x);
            }
        }
    };

    int nk = K >> 5;
    if (STAGES == 2) {
        cpA(0, 0); cpB(0, 0); cp_commit();
        cpA(1, 1); cpB(1, 1); cp_commit();
        for (int kb = 0; kb < nk; ++kb) {
            cp_wait<1>();
            __syncthreads();
            compute(kb & 1);
            __syncthreads();
            if (kb + 2 < nk) { cpA(kb & 1, kb + 2); cpB(kb & 1, kb + 2); }
            cp_commit();
        }
    } else {
        cpA(0, 0); cpB(0, 0); cp_commit();
        cpA(1, 1); cpB(1, 1); cp_commit();
        for (int kb = 0; kb < nk; ++kb) {
            cp_wait<1>();
            __syncthreads();
            compute(kb % 3);
            if (kb + 2 < nk) {
                int nb = (kb + 2) % 3;
                cpA(nb, kb + 2); cpB(nb, kb + 2);
            }
            cp_commit();
        }
    }

    #pragma unroll
    for (int mi = 0; mi < 2; ++mi) {
        #pragma unroll
        for (int half = 0; half < 2; ++half) {
            int row = m0 + m0w + mi * 16 + g + half * 8;
            float sc = HAS_SC ? scaleA[row] : 1.f;
            #pragma unroll
            for (int ni = 0; ni < NI; ++ni) {
                int col = n0 + n0w + ni * 8 + 2 * q;
                if (col >= N) continue;
                float v0 = sc * acc[mi][ni][half * 2 + 0];
                float v1 = sc * acc[mi][ni][half * 2 + 1];
                if (EPI == 1) { v0 += bias[col]; v1 += bias[col + 1]; }
                else if (EPI == 2) {
                    v0 += bias[col]; v1 += bias[col + 1];
                    v0 = 0.5f * v0 * (1.f + erff(v0 * 0.70710678118654752f));
                    v1 = 0.5f * v1 * (1.f + erff(v1 * 0.70710678118654752f));
                } else if (EPI == 3) {
                    const float* rp = res + (size_t)row * N + col;
                    v0 += rp[0]; v1 += rp[1];
                }
                *(float2*)(C + (size_t)row * N + col) = make_float2(v0, v1);
            }
        }
    }
}

#define TG4_SMEM_NI8 ((2*A_ST + 2*(128*BQ))*8)     // 81920
#define TG4_SMEM_NI4 ((3*A_ST + 3*(64*BQ))*8)      // 92160

// ---------------- conv: 8-token smem tiles ----------------
#define CT 8
__global__ void __launch_bounds__(256) conv_kernel(
    const float* __restrict__ cw, const float* __restrict__ cb,
    const float* __restrict__ dtb, const float* __restrict__ alog) {
    __shared__ float4 sz[CT + 3][160];
    __shared__ float4 scw[CDIM];
    __shared__ float  scb[CDIM];
    int tid = threadIdx.x;
    int blk = blockIdx.x;
    int b = blk >> 8;
    int t0 = (blk & 255) * CT;

    for (int i = tid; i < CDIM; i += 256) {
        scw[i] = ((const float4*)cw)[i];
        scb[i] = cb[i];
    }
    for (int i = tid; i < (CT + 3) * 160; i += 256) {
        int rr = i / 160, c4 = i - rr * 160;
        int t = t0 - 3 + rr;
        float4 v = make_float4(0.f, 0.f, 0.f, 0.f);
        if (t >= 0)
            v = *(const float4*)(g_z + (size_t)(b * SEQ + t) * DIP + DINNER + c4 * 4);
        sz[rr][c4] = v;
    }
    __syncthreads();

    for (int i = tid; i < CT * 160; i += 256) {
        int s = i / 160, c4 = i - s * 160;
        int c = c4 * 4;
        float4 w0 = scw[c], w1 = scw[c + 1], w2 = scw[c + 2], w3 = scw[c + 3];
        float4 z0 = sz[s][c4], z1 = sz[s + 1][c4], z2 = sz[s + 2][c4], z3 = sz[s + 3][c4];
        float a0 = scb[c    ] + z0.x * w0.x + z1.x * w0.y + z2.x * w0.z + z3.x * w0.w;
        float a1 = scb[c + 1] + z0.y * w1.x + z1.y * w1.y + z2.y * w1.z + z3.y * w1.w;
        float a2 = scb[c + 2] + z0.z * w2.x + z1.z * w2.y + z2.z * w2.z + z3.z * w2.w;
        float a3 = scb[c + 3] + z0.w * w3.x + z1.w * w3.y + z2.w * w3.z + z3.w * w3.w;
        float4 o = make_float4(siluf(a0), siluf(a1), siluf(a2), siluf(a3));
        *(float4*)(g_xbc + (size_t)(b * SEQ + t0 + s) * CDIM + c) = o;
    }

    if (tid < CT * NHEADS) {
        int s = tid >> 3, hh = tid & 7;
        int r = b * SEQ + t0 + s;
        float v = g_z[(size_t)r * DIP + (DIP - NHEADS) + hh] + dtb[hh];
        float dt = (v > 20.f) ? v : log1pf(expf(v));
        float dA = expf(-dt * expf(alog[hh]));
        g_dtA[r * NHEADS + hh] = make_float2(dt, dA);
    }
}

// ---------------- selective scan ----------------
#define SDEPTH 8

__global__ void __launch_bounds__(256) scan_kernel(const float* __restrict__ Dp) {
    int pz = blockIdx.x;
    int h  = blockIdx.y;
    int b  = blockIdx.z;
    int tid = threadIdx.x;
    int w = tid >> 5, lane = tid & 31;
    int p_sub = lane >> 3;
    int n_sub = lane & 7;
    int p = pz * 32 + w * 4 + p_sub;

    const float* base = g_xbc + (size_t)b * SEQ * CDIM;
    const float2* dbase = g_dtA + (size_t)b * SEQ * NHEADS + h;
    float* ybase = g_y + (size_t)b * SEQ * DINNER + h * HEADDIM + p;
    float Dv = Dp[h];

    float hs[8];
    #pragma unroll
    for (int j = 0; j < 8; ++j) hs[j] = 0.f;

    float4 Bb[SDEPTH][2], Cb[SDEPTH][2];
    float  xb[SDEPTH];
    float2 db[SDEPTH];

    const int boff = DINNER + n_sub * 8;
    const int coff = DINNER + DSTATE + n_sub * 8;
    const int xoff = h * HEADDIM + p;

    #pragma unroll
    for (int s = 0; s < SDEPTH; ++s) {
        const float* row = base + (size_t)s * CDIM;
        Bb[s][0] = *(const float4*)(row + boff);
        Bb[s][1] = *(const float4*)(row + boff + 4);
        Cb[s][0] = *(const float4*)(row + coff);
        Cb[s][1] = *(const float4*)(row + coff + 4);
        xb[s] = row[xoff];
        db[s] = dbase[(size_t)s * NHEADS];
    }

    for (int t0 = 0; t0 < SEQ; t0 += SDEPTH) {
        #pragma unroll
        for (int s = 0; s < SDEPTH; ++s) {
            int t = t0 + s;
            float dtv = db[s].x, dAv = db[s].y;
            float xv = xb[s];
            float cbm = dtv * xv;
            float4 B0 = Bb[s][0], B1 = Bb[s][1];
            float4 C0 = Cb[s][0], C1 = Cb[s][1];
            float acc;
            hs[0] = fmaf(hs[0], dAv, cbm * B0.x); acc = hs[0] * C0.x;
            hs[1] = fmaf(hs[1], dAv, cbm * B0.y); acc = fmaf(hs[1], C0.y, acc);
            hs[2] = fmaf(hs[2], dAv, cbm * B0.z); acc = fmaf(hs[2], C0.z, acc);
            hs[3] = fmaf(hs[3], dAv, cbm * B0.w); acc = fmaf(hs[3], C0.w, acc);
            hs[4] = fmaf(hs[4], dAv, cbm * B1.x); acc = fmaf(hs[4], C1.x, acc);
            hs[5] = fmaf(hs[5], dAv, cbm * B1.y); acc = fmaf(hs[5], C1.y, acc);
            hs[6] = fmaf(hs[6], dAv, cbm * B1.z); acc = fmaf(hs[6], C1.z, acc);
            hs[7] = fmaf(hs[7], dAv, cbm * B1.w); acc = fmaf(hs[7], C1.w, acc);
            acc += __shfl_xor_sync(0xffffffffu, acc, 1);
            acc += __shfl_xor_sync(0xffffffffu, acc, 2);
            acc += __shfl_xor_sync(0xffffffffu, acc, 4);
            if (n_sub == 0)
                ybase[(size_t)t * DINNER] = acc + Dv * xv;
            int tn = t + SDEPTH;
            if (tn > SEQ - 1) tn = SEQ - 1;
            const float* row = base + (size_t)tn * CDIM;
            Bb[s][0] = *(const float4*)(row + boff);
            Bb[s][1] = *(const float4*)(row + boff + 4);
            Cb[s][0] = *(const float4*)(row + coff);
            Cb[s][1] = *(const float4*)(row + coff + 4);
            xb[s] = row[xoff];
            db[s] = dbase[(size_t)tn * NHEADS];
        }
    }
}

// ---------------- mlp2 ----------------
__global__ void __launch_bounds__(256) mlp2_kernel(
    const float* __restrict__ W2, const float* __restrict__ b2, float* __restrict__ out) {
    __shared__ float Ws[EMB * 5];
    __shared__ float bs[5];
    int tid = threadIdx.x;
    for (int i = tid; i < EMB * 5; i += 256) Ws[i] = W2[i];
    if (tid < 5) bs[tid] = b2[tid];
    __syncthreads();
    int warp = tid >> 5, lane = tid & 31;
    int tok = blockIdx.x * 8 + warp;
    float a0=0,a1=0,a2=0,a3=0,a4=0;
    for (int k = lane; k < EMB; k += 32) {
        float hv = g_h1[(size_t)tok * EMB + k];
        a0 = fmaf(hv, Ws[k * 5 + 0], a0);
        a1 = fmaf(hv, Ws[k * 5 + 1], a1);
        a2 = fmaf(hv, Ws[k * 5 + 2], a2);
        a3 = fmaf(hv, Ws[k * 5 + 3], a3);
        a4 = fmaf(hv, Ws[k * 5 + 4], a4);
    }
    #pragma unroll
    for (int o = 16; o; o >>= 1) {
        a0 += __shfl_xor_sync(0xffffffffu, a0, o);
        a1 += __shfl_xor_sync(0xffffffffu, a1, o);
        a2 += __shfl_xor_sync(0xffffffffu, a2, o);
        a3 += __shfl_xor_sync(0xffffffffu, a3, o);
        a4 += __shfl_xor_sync(0xffffffffu, a4, o);
    }
    if (lane == 0) {
        out[(size_t)tok * 5 + 0] = a0 + bs[0];
        out[(size_t)tok * 5 + 1] = a1 + bs[1];
        out[(size_t)tok * 5 + 2] = a2 + bs[2];
        out[(size_t)tok * 5 + 3] = a3 + bs[3];
        out[(size_t)tok * 5 + 4] = a4 + bs[4];
    }
}

// ---------------- host launcher ----------------
extern "C" void kernel_launch(void* const* d_in, const int* in_sizes, int n_in,
                              void* d_out, int out_size) {
    const float* feature     = (const float*)d_in[0];
    const float* w_avg       = (const float*)d_in[1];
    const float* inproj_ln_g = (const float*)d_in[2];
    const float* inproj_ln_b = (const float*)d_in[3];
    const float* inproj_W    = (const float*)d_in[4];
    const float* inproj_b    = (const float*)d_in[5];
    const float* rms_w       = (const float*)d_in[6];
    const float* m_inW       = (const float*)d_in[7];
    const float* m_convW     = (const float*)d_in[8];
    const float* m_convB     = (const float*)d_in[9];
    const float* m_dtb       = (const float*)d_in[10];
    const float* m_Alog      = (const float*)d_in[11];
    const float* m_D         = (const float*)d_in[12];
    const float* m_gnw       = (const float*)d_in[13];
    const float* m_outW      = (const float*)d_in[14];
    const float* norm_w      = (const float*)d_in[15];
    const float* mlp_ln_g    = (const float*)d_in[16];
    const float* mlp_ln_b    = (const float*)d_in[17];
    const float* mlp_W1      = (const float*)d_in[18];
    const float* mlp_b1      = (const float*)d_in[19];
    const float* mlp_W2      = (const float*)d_in[20];
    const float* mlp_b2      = (const float*)d_in[21];
    float* out = (float*)d_out;

    float *x, *z, *h1, *ascale;
    unsigned long long *wt_in, *wt_minw, *wt_mout, *wt_mlp1, *apk;
    cudaGetSymbolAddress((void**)&x,  g_x);
    cudaGetSymbolAddress((void**)&z,  g_z);
    cudaGetSymbolAddress((void**)&h1, g_h1);
    cudaGetSymbolAddress((void**)&apk, g_apk);
    cudaGetSymbolAddress((void**)&ascale, g_ascale);
    cudaGetSymbolAddress((void**)&wt_in,   g_wt_in);
    cudaGetSymbolAddress((void**)&wt_minw, g_wt_minw);
    cudaGetSymbolAddress((void**)&wt_mout, g_wt_mout);
    cudaGetSymbolAddress((void**)&wt_mlp1, g_wt_mlp1);

    cudaFuncSetAttribute(tgemm4_kernel<1,4,0>, cudaFuncAttributeMaxDynamicSharedMemorySize, TG4_SMEM_NI4);
    cudaFuncSetAttribute(tgemm4_kernel<0,8,1>, cudaFuncAttributeMaxDynamicSharedMemorySize, TG4_SMEM_NI8);
    cudaFuncSetAttribute(tgemm4_kernel<3,4,1>, cudaFuncAttributeMaxDynamicSharedMemorySize, TG4_SMEM_NI4);
    cudaFuncSetAttribute(tgemm4_kernel<2,4,0>, cudaFuncAttributeMaxDynamicSharedMemorySize, TG4_SMEM_NI4);

    // index 3 = pure-async NI4 GEMM (ncu capture slot)
    convw_kernel<<<64, 256>>>(inproj_W, wt_in, 128, 256, 256);                      // 0
    softmax_kernel<<<1, 32>>>(w_avg, NFEAT);                                        // 1
    avg_ln_kernel<<<TOK / 8, 256>>>(feature, inproj_ln_g, inproj_ln_b, apk);        // 2
    tgemm4_kernel<1,4,0><<<dim3(4, TOK / 128), 256, TG4_SMEM_NI4>>>(
        apk, nullptr, wt_in, inproj_b, nullptr, x, TOK, EMB, DMODEL);               // 3 <- captured

    for (int i = 0; i < NLAYERS; ++i) {
        convw_kernel<<<640, 256>>>(m_inW + (size_t)i * EMB * DIP,
                                   wt_minw + (size_t)i * DIPPAD * 128, 256, DIP, DIPPAD);
        convw_kernel<<<256, 256>>>(m_outW + (size_t)i * DINNER * EMB,
                                   wt_mout + (size_t)i * 256 * 256, 512, 256, 256);
    }
    convw_kernel<<<128, 256>>>(mlp_W1, wt_mlp1, 256, 256, 256);

    for (int i = 0; i < NLAYERS; ++i) {
        pack_rms_kernel<<<TOK / 8, 256>>>(x, rms_w + (size_t)i * EMB, apk, ascale);
        // z = rmsnorm(x) @ m_inW[i]  (16384x256 @ 256x1160)
        tgemm4_kernel<0,8,1><<<dim3(DIPPAD / 128, TOK / 128), 256, TG4_SMEM_NI8>>>(
            apk, ascale, wt_minw + (size_t)i * DIPPAD * 128,
            nullptr, nullptr, z, TOK, DIP, EMB);
        conv_kernel<<<TOK / CT, 256>>>(m_convW + (size_t)i * CDIM * DCONV,
                                       m_convB + (size_t)i * CDIM,
                                       m_dtb + i * NHEADS, m_Alog + i * NHEADS);
        scan_kernel<<<dim3(2, NHEADS, BATCH), 256>>>(m_D + i * NHEADS);
        pack_gate_kernel<<<TOK / 8, 256>>>(m_gnw + (size_t)i * DINNER, apk, ascale);
        // x = rmsnorm(y*silu(z)) @ m_outW[i] + x  (16384x512 @ 512x256)
        tgemm4_kernel<3,4,1><<<dim3(4, TOK / 128), 256, TG4_SMEM_NI4>>>(
            apk, ascale, wt_mout + (size_t)i * 256 * 256,
            nullptr, x, x, TOK, EMB, DINNER);
    }

    finalnorm_kernel<<<TOK / 8, 256>>>(norm_w, mlp_ln_g, mlp_ln_b, apk);
    // h1 = gelu(xn @ W1 + b1)
    tgemm4_kernel<2,4,0><<<dim3(4, TOK / 128), 256, TG4_SMEM_NI4>>>(
        apk, nullptr, wt_mlp1, mlp_b1, nullptr, h1, TOK, EMB, EMB);
    mlp2_kernel<<<TOK / 8, 256>>>(mlp_W2, mlp_b2, out);
}